// round 4
// baseline (speedup 1.0000x reference)
#include <cuda_runtime.h>
#include <stdint.h>

#define N_NODES 100000
#define N_EDGES 1600000
#define NF      128
#define NC      40
#define MASK_N  (N_NODES * NF)     // 12,800,000

// ---------------- static scratch (no allocations allowed) ----------------
static __device__ float         g_h[(size_t)N_NODES * NF];    // 51.2 MB
static __device__ float         g_t2[(size_t)N_NODES * NC];   // 16 MB
static __device__ float         g_dinv[N_NODES];
static __device__ int           g_cnt[N_NODES];
static __device__ int           g_rowptr[N_NODES + 1];
static __device__ int           g_cursor[N_NODES];
static __device__ int           g_csr_src[N_EDGES];           // 6.4 MB
static __device__ unsigned char g_mask[MASK_N];               // 12.8 MB
static __device__ int           g_blocksum[256];

// ---------------- threefry2x32, key = (0, 42) ----------------
__device__ __forceinline__ uint32_t rotl32(uint32_t x, int r) {
    return (x << r) | (x >> (32 - r));
}

__device__ __forceinline__ void threefry_0_42(uint32_t& x0, uint32_t& x1) {
    const uint32_t K1 = 0u;
    const uint32_t K2 = 42u;
    const uint32_t KC = 0x1BD11BDAu ^ K1 ^ K2;  // 0x1BD11BF0
#define TF_ROUND(r) { x0 += x1; x1 = rotl32(x1, r); x1 ^= x0; }
    x0 += K1; x1 += K2;
    TF_ROUND(13) TF_ROUND(15) TF_ROUND(26) TF_ROUND(6)
    x0 += K2; x1 += KC + 1u;
    TF_ROUND(17) TF_ROUND(29) TF_ROUND(16) TF_ROUND(24)
    x0 += KC; x1 += K1 + 2u;
    TF_ROUND(13) TF_ROUND(15) TF_ROUND(26) TF_ROUND(6)
    x0 += K1; x1 += K2 + 3u;
    TF_ROUND(17) TF_ROUND(29) TF_ROUND(16) TF_ROUND(24)
    x0 += K2; x1 += KC + 4u;
    TF_ROUND(13) TF_ROUND(15) TF_ROUND(26) TF_ROUND(6)
    x0 += KC; x1 += K1 + 5u;
#undef TF_ROUND
}

// ---------------- small kernels: degree / CSR build ----------------
__global__ void k_zero(int N) {
    int i = blockIdx.x * blockDim.x + threadIdx.x;
    if (i < N) g_cnt[i] = 0;
}

__global__ void k_count(const int* __restrict__ ei, int E) {
    int e = blockIdx.x * blockDim.x + threadIdx.x;
    if (e < E) atomicAdd(&g_cnt[ei[E + e]], 1);
}

__global__ void k_scan1(int N) {  // blockDim = 1024: block reduce -> blocksum
    __shared__ int s[1024];
    int t = threadIdx.x;
    int i = blockIdx.x * 1024 + t;
    s[t] = (i < N) ? g_cnt[i] : 0;
    __syncthreads();
    for (int off = 512; off > 0; off >>= 1) {
        if (t < off) s[t] += s[t + off];
        __syncthreads();
    }
    if (t == 0) g_blocksum[blockIdx.x] = s[0];
}

__global__ void k_scan2(int nb, int N) {  // 1 thread: scan block sums
    if (threadIdx.x == 0 && blockIdx.x == 0) {
        int acc = 0;
        for (int b = 0; b < nb; b++) {
            int v = g_blocksum[b];
            g_blocksum[b] = acc;
            acc += v;
        }
        g_rowptr[N] = acc;
    }
}

__global__ void k_scan3(int N) {  // blockDim = 1024: in-block exclusive scan
    __shared__ int s[1024];
    int t = threadIdx.x;
    int i = blockIdx.x * 1024 + t;
    int v = (i < N) ? g_cnt[i] : 0;
    s[t] = v;
    __syncthreads();
    for (int off = 1; off < 1024; off <<= 1) {
        int x = (t >= off) ? s[t - off] : 0;
        __syncthreads();
        s[t] += x;
        __syncthreads();
    }
    if (i < N) {
        int excl = s[t] - v + g_blocksum[blockIdx.x];
        g_rowptr[i] = excl;
        g_cursor[i] = excl;
        g_dinv[i]   = rsqrtf((float)(v + 1));  // +1 self loop
    }
}

__global__ void k_fill(const int* __restrict__ ei, int E) {
    int e = blockIdx.x * blockDim.x + threadIdx.x;
    if (e < E) {
        int d   = ei[E + e];
        int pos = atomicAdd(&g_cursor[d], 1);
        g_csr_src[pos] = ei[e];
    }
}

// ---------------- dropout mask (threefry_partitionable=True path) --------
// Per element i: counter is the 64-bit linear index -> inputs (hi,lo)=(0,i).
// 32-bit random bits = out0 ^ out1. keep iff uniform >= 0.5 iff MSB set.
// Each thread handles 4 consecutive elements and writes one uchar4.
__global__ void k_mask() {
    int q = blockIdx.x * blockDim.x + threadIdx.x;   // quad index
    if (q < MASK_N / 4) {
        uint32_t base = (uint32_t)q * 4u;
        uchar4 m;
        {
            uint32_t a = 0u, b = base + 0u;
            threefry_0_42(a, b);
            m.x = (unsigned char)((a ^ b) >> 31);
        }
        {
            uint32_t a = 0u, b = base + 1u;
            threefry_0_42(a, b);
            m.y = (unsigned char)((a ^ b) >> 31);
        }
        {
            uint32_t a = 0u, b = base + 2u;
            threefry_0_42(a, b);
            m.z = (unsigned char)((a ^ b) >> 31);
        }
        {
            uint32_t a = 0u, b = base + 3u;
            threefry_0_42(a, b);
            m.w = (unsigned char)((a ^ b) >> 31);
        }
        *(uchar4*)(g_mask + (size_t)base) = m;
    }
}

// ---------------- GEMM1: h = x @ W1  (M x 128 x 128, fp32) ----------------
// blockDim = 256, tile 64 rows x 128 cols, thread micro-tile 4x8.
__global__ void k_gemm1(const float* __restrict__ x,
                        const float* __restrict__ W,
                        int M) {
    __shared__ __align__(16) float Xs[64][33];
    __shared__ __align__(16) float Ws[32][128];

    int row0 = blockIdx.x * 64;
    int tx = threadIdx.x % 16;  // 16 col groups * 8 cols
    int ty = threadIdx.x / 16;  // 16 row groups * 4 rows

    float acc[4][8];
#pragma unroll
    for (int i = 0; i < 4; i++)
#pragma unroll
        for (int j = 0; j < 8; j++) acc[i][j] = 0.f;

    for (int k0 = 0; k0 < 128; k0 += 32) {
        // load X tile: 64 rows x 32 cols
        {
            int r  = threadIdx.x / 8;         // 0..31
            int c4 = (threadIdx.x % 8) * 4;   // 0..28
#pragma unroll
            for (int rr = r; rr < 64; rr += 32) {
                int grow = row0 + rr;
                float4 v = make_float4(0.f, 0.f, 0.f, 0.f);
                if (grow < M)
                    v = *(const float4*)(x + (size_t)grow * 128 + k0 + c4);
                Xs[rr][c4 + 0] = v.x;
                Xs[rr][c4 + 1] = v.y;
                Xs[rr][c4 + 2] = v.z;
                Xs[rr][c4 + 3] = v.w;
            }
        }
        // load W tile: 32 rows x 128 cols = 1024 float4
        for (int i = threadIdx.x; i < 32 * 32; i += 256) {
            int kr = i / 32;
            int cc = (i % 32) * 4;
            *(float4*)(&Ws[kr][cc]) =
                *(const float4*)(W + (size_t)(k0 + kr) * 128 + cc);
        }
        __syncthreads();

#pragma unroll
        for (int kk = 0; kk < 32; kk++) {
            float a0 = Xs[ty * 4 + 0][kk];
            float a1 = Xs[ty * 4 + 1][kk];
            float a2 = Xs[ty * 4 + 2][kk];
            float a3 = Xs[ty * 4 + 3][kk];
            float4 b0 = *(const float4*)(&Ws[kk][tx * 8]);
            float4 b1 = *(const float4*)(&Ws[kk][tx * 8 + 4]);
            float bb[8] = {b0.x, b0.y, b0.z, b0.w, b1.x, b1.y, b1.z, b1.w};
            float aa[4] = {a0, a1, a2, a3};
#pragma unroll
            for (int i = 0; i < 4; i++)
#pragma unroll
                for (int j = 0; j < 8; j++)
                    acc[i][j] = fmaf(aa[i], bb[j], acc[i][j]);
        }
        __syncthreads();
    }

    int col = tx * 8;
#pragma unroll
    for (int i = 0; i < 4; i++) {
        int grow = row0 + ty * 4 + i;
        if (grow < M) {
            float4 v0 = make_float4(acc[i][0], acc[i][1], acc[i][2], acc[i][3]);
            float4 v1 = make_float4(acc[i][4], acc[i][5], acc[i][6], acc[i][7]);
            *(float4*)(g_h + (size_t)grow * 128 + col)     = v0;
            *(float4*)(g_h + (size_t)grow * 128 + col + 4) = v1;
        }
    }
}

// ---------------- fused: agg1 + b1 + ReLU + dropout + GEMM2 (128->40) -----
// one warp per dst node; 8 warps / block of 256 threads.
__global__ void k_agg1_fused(const float* __restrict__ b1,
                             const float* __restrict__ W2,
                             int N) {
    __shared__ __align__(16) float Ws2[128 * NC];  // 20 KB
    __shared__ __align__(16) float b1s[128];

    for (int i = threadIdx.x; i < 128 * NC; i += blockDim.x) Ws2[i] = W2[i];
    if (threadIdx.x < 128) b1s[threadIdx.x] = b1[threadIdx.x];
    __syncthreads();

    int warp = threadIdx.x >> 5;
    int lane = threadIdx.x & 31;
    int n = blockIdx.x * (blockDim.x >> 5) + warp;
    if (n >= N) return;

    float di = g_dinv[n];
    float wself = di * di;

    // self-loop init: acc = h[n] * dinv^2
    float4 acc = ((const float4*)(g_h + (size_t)n * 128))[lane];
    acc.x *= wself; acc.y *= wself; acc.z *= wself; acc.w *= wself;

    int e0 = g_rowptr[n];
    int e1 = g_rowptr[n + 1];
    for (int e = e0; e < e1; e++) {
        int s   = g_csr_src[e];
        float w = g_dinv[s] * di;
        float4 v = ((const float4*)(g_h + (size_t)s * 128))[lane];
        acc.x = fmaf(v.x, w, acc.x);
        acc.y = fmaf(v.y, w, acc.y);
        acc.z = fmaf(v.z, w, acc.z);
        acc.w = fmaf(v.w, w, acc.w);
    }

    // + b1, ReLU, dropout (keep -> *2, drop -> 0)
    float4 bb = ((const float4*)b1s)[lane];
    uchar4 mk = *(const uchar4*)(g_mask + (size_t)n * 128 + lane * 4);
    float fc[4];
    fc[0] = fmaxf(acc.x + bb.x, 0.f) * (mk.x ? 2.f : 0.f);
    fc[1] = fmaxf(acc.y + bb.y, 0.f) * (mk.y ? 2.f : 0.f);
    fc[2] = fmaxf(acc.z + bb.z, 0.f) * (mk.z ? 2.f : 0.f);
    fc[3] = fmaxf(acc.w + bb.w, 0.f) * (mk.w ? 2.f : 0.f);

    // GEMM2 via shuffle broadcast: t2[n][c] = sum_k hd[k] * W2[k][c]
    int c1 = 32 + (lane & 7);
    float o0 = 0.f, o1 = 0.f;
#pragma unroll 4
    for (int k = 0; k < 128; k++) {
        float v = __shfl_sync(0xffffffffu, fc[k & 3], k >> 2);
        o0 = fmaf(v, Ws2[k * NC + lane], o0);
        o1 = fmaf(v, Ws2[k * NC + c1], o1);
    }

    float* tp = g_t2 + (size_t)n * NC;
    tp[lane] = o0;
    if (lane < 8) tp[c1] = o1;
}

// ---------------- agg2: out = A_norm @ t2 + b2  (width 40) ----------------
__global__ void k_agg2(const float* __restrict__ b2,
                       float* __restrict__ out,
                       int N) {
    int warp = threadIdx.x >> 5;
    int lane = threadIdx.x & 31;
    int n = blockIdx.x * (blockDim.x >> 5) + warp;
    if (n >= N) return;

    float di = g_dinv[n];
    float wself = di * di;
    int c0 = lane;
    int c1 = 32 + (lane & 7);

    const float* tn = g_t2 + (size_t)n * NC;
    float a0 = tn[c0] * wself;
    float a1 = tn[c1] * wself;

    int e0 = g_rowptr[n];
    int e1 = g_rowptr[n + 1];
    for (int e = e0; e < e1; e++) {
        int s   = g_csr_src[e];
        float w = g_dinv[s] * di;
        const float* ts = g_t2 + (size_t)s * NC;
        a0 = fmaf(ts[c0], w, a0);
        a1 = fmaf(ts[c1], w, a1);
    }

    out[(size_t)n * NC + c0] = a0 + b2[c0];
    if (lane < 8) out[(size_t)n * NC + c1] = a1 + b2[c1];
}

// ---------------- launch ----------------
extern "C" void kernel_launch(void* const* d_in, const int* in_sizes, int n_in,
                              void* d_out, int out_size) {
    const float* x  = (const float*)d_in[0];
    const int*   ei = (const int*)d_in[1];
    const float* W1 = (const float*)d_in[2];
    const float* b1 = (const float*)d_in[3];
    const float* W2 = (const float*)d_in[4];
    const float* b2 = (const float*)d_in[5];
    float* out = (float*)d_out;

    const int N = N_NODES;
    const int E = N_EDGES;
    const int nb = (N + 1023) / 1024;

    k_zero  <<<(N + 255) / 256, 256>>>(N);
    k_count <<<(E + 255) / 256, 256>>>(ei, E);
    k_scan1 <<<nb, 1024>>>(N);
    k_scan2 <<<1, 32>>>(nb, N);
    k_scan3 <<<nb, 1024>>>(N);
    k_fill  <<<(E + 255) / 256, 256>>>(ei, E);
    k_mask  <<<(MASK_N / 4 + 255) / 256, 256>>>();
    k_gemm1 <<<(N + 63) / 64, 256>>>(x, W1, N);
    k_agg1_fused <<<(N + 7) / 8, 256>>>(b1, W2, N);
    k_agg2       <<<(N + 7) / 8, 256>>>(b2, out, N);
}

// round 5
// speedup vs baseline: 1.1335x; 1.1335x over previous
#include <cuda_runtime.h>
#include <stdint.h>

#define N_NODES 100000
#define N_EDGES 1600000
#define NF      128
#define NC      40

// ---------------- static scratch (no allocations allowed) ----------------
static __device__ float g_h[(size_t)N_NODES * NF];    // 51.2 MB
static __device__ float g_t2[(size_t)N_NODES * NC];   // 16 MB
static __device__ float g_dinv[N_NODES];
static __device__ int   g_cnt[N_NODES];
static __device__ int   g_rowptr[N_NODES + 1];
static __device__ int   g_cursor[N_NODES];
static __device__ int   g_csr_src[N_EDGES];           // 6.4 MB
static __device__ int   g_blocksum[128];

// ---------------- packed f32x2 helpers (Blackwell dual-rate fp32) --------
__device__ __forceinline__ uint64_t pack2(float lo, float hi) {
    uint64_t r;
    asm("mov.b64 %0, {%1, %2};" : "=l"(r) : "f"(lo), "f"(hi));
    return r;
}
__device__ __forceinline__ void fma2(uint64_t& d, uint64_t a, uint64_t b) {
    asm("fma.rn.f32x2 %0, %1, %2, %0;" : "+l"(d) : "l"(a), "l"(b));
}
__device__ __forceinline__ float2 unpack2(uint64_t v) {
    float2 f;
    asm("mov.b64 {%0, %1}, %2;" : "=f"(f.x), "=f"(f.y) : "l"(v));
    return f;
}

// ---------------- threefry2x32, key = (0, 42) ----------------
__device__ __forceinline__ uint32_t rotl32(uint32_t x, int r) {
    return (x << r) | (x >> (32 - r));
}

__device__ __forceinline__ void threefry_0_42(uint32_t& x0, uint32_t& x1) {
    const uint32_t K1 = 0u;
    const uint32_t K2 = 42u;
    const uint32_t KC = 0x1BD11BDAu ^ K1 ^ K2;  // 0x1BD11BF0
#define TF_ROUND(r) { x0 += x1; x1 = rotl32(x1, r); x1 ^= x0; }
    x0 += K1; x1 += K2;
    TF_ROUND(13) TF_ROUND(15) TF_ROUND(26) TF_ROUND(6)
    x0 += K2; x1 += KC + 1u;
    TF_ROUND(17) TF_ROUND(29) TF_ROUND(16) TF_ROUND(24)
    x0 += KC; x1 += K1 + 2u;
    TF_ROUND(13) TF_ROUND(15) TF_ROUND(26) TF_ROUND(6)
    x0 += K1; x1 += K2 + 3u;
    TF_ROUND(17) TF_ROUND(29) TF_ROUND(16) TF_ROUND(24)
    x0 += K2; x1 += KC + 4u;
    TF_ROUND(13) TF_ROUND(15) TF_ROUND(26) TF_ROUND(6)
    x0 += KC; x1 += K1 + 5u;
#undef TF_ROUND
}

// keep-mask (partitionable threefry): element i -> counter (0, i),
// bits = out0 ^ out1, keep iff MSB set. Returns 2.0f (keep) or 0.0f (drop).
__device__ __forceinline__ float drop_scale(uint32_t i) {
    uint32_t a = 0u, b = i;
    threefry_0_42(a, b);
    return ((a ^ b) >> 31) ? 2.0f : 0.0f;
}

// ---------------- small kernels: degree / CSR build ----------------
__global__ void k_zero(int N) {
    int i = blockIdx.x * blockDim.x + threadIdx.x;
    if (i < N) g_cnt[i] = 0;
}

__global__ void k_count(const int* __restrict__ ei, int E) {
    int e = blockIdx.x * blockDim.x + threadIdx.x;
    if (e < E) atomicAdd(&g_cnt[ei[E + e]], 1);
}

__global__ void k_scan1(int N) {  // blockDim = 1024: block reduce -> blocksum
    __shared__ int s[1024];
    int t = threadIdx.x;
    int i = blockIdx.x * 1024 + t;
    s[t] = (i < N) ? g_cnt[i] : 0;
    __syncthreads();
    for (int off = 512; off > 0; off >>= 1) {
        if (t < off) s[t] += s[t + off];
        __syncthreads();
    }
    if (t == 0) g_blocksum[blockIdx.x] = s[0];
}

__global__ void k_scan2(int nb, int N) {  // one 128-thread block scan
    __shared__ int s[128];
    int t = threadIdx.x;
    int v = (t < nb) ? g_blocksum[t] : 0;
    s[t] = v;
    __syncthreads();
    for (int off = 1; off < 128; off <<= 1) {
        int x = (t >= off) ? s[t - off] : 0;
        __syncthreads();
        s[t] += x;
        __syncthreads();
    }
    if (t < nb) g_blocksum[t] = s[t] - v;   // exclusive
    if (t == 127) g_rowptr[N] = s[127];     // total
}

__global__ void k_scan3(int N) {  // blockDim = 1024: in-block exclusive scan
    __shared__ int s[1024];
    int t = threadIdx.x;
    int i = blockIdx.x * 1024 + t;
    int v = (i < N) ? g_cnt[i] : 0;
    s[t] = v;
    __syncthreads();
    for (int off = 1; off < 1024; off <<= 1) {
        int x = (t >= off) ? s[t - off] : 0;
        __syncthreads();
        s[t] += x;
        __syncthreads();
    }
    if (i < N) {
        int excl = s[t] - v + g_blocksum[blockIdx.x];
        g_rowptr[i] = excl;
        g_cursor[i] = excl;
        g_dinv[i]   = rsqrtf((float)(v + 1));  // +1 self loop
    }
}

__global__ void k_fill(const int* __restrict__ ei, int E) {
    int e = blockIdx.x * blockDim.x + threadIdx.x;
    if (e < E) {
        int d   = ei[E + e];
        int pos = atomicAdd(&g_cursor[d], 1);
        g_csr_src[pos] = ei[e];
    }
}

// ---------------- GEMM1: h = x @ W1  (M x 128 x 128, fp32, f32x2) --------
// blockDim = 256, tile 64 rows x 128 cols, thread micro-tile 4x8 (4 pairs).
__global__ void k_gemm1(const float* __restrict__ x,
                        const float* __restrict__ W,
                        int M) {
    __shared__ __align__(16) float Xs[64][33];
    __shared__ __align__(16) float Ws[32][128];

    int row0 = blockIdx.x * 64;
    int tx = threadIdx.x % 16;  // 16 col groups * 8 cols
    int ty = threadIdx.x / 16;  // 16 row groups * 4 rows

    uint64_t acc[4][4];
#pragma unroll
    for (int i = 0; i < 4; i++)
#pragma unroll
        for (int j = 0; j < 4; j++) acc[i][j] = pack2(0.f, 0.f);

    for (int k0 = 0; k0 < 128; k0 += 32) {
        {
            int r  = threadIdx.x / 8;         // 0..31
            int c4 = (threadIdx.x % 8) * 4;   // 0..28
#pragma unroll
            for (int rr = r; rr < 64; rr += 32) {
                int grow = row0 + rr;
                float4 v = make_float4(0.f, 0.f, 0.f, 0.f);
                if (grow < M)
                    v = *(const float4*)(x + (size_t)grow * 128 + k0 + c4);
                Xs[rr][c4 + 0] = v.x;
                Xs[rr][c4 + 1] = v.y;
                Xs[rr][c4 + 2] = v.z;
                Xs[rr][c4 + 3] = v.w;
            }
        }
        for (int i = threadIdx.x; i < 32 * 32; i += 256) {
            int kr = i / 32;
            int cc = (i % 32) * 4;
            *(float4*)(&Ws[kr][cc]) =
                *(const float4*)(W + (size_t)(k0 + kr) * 128 + cc);
        }
        __syncthreads();

#pragma unroll
        for (int kk = 0; kk < 32; kk++) {
            const uint64_t* bp = (const uint64_t*)(&Ws[kk][tx * 8]);
            uint64_t b0 = bp[0], b1 = bp[1], b2 = bp[2], b3 = bp[3];
#pragma unroll
            for (int i = 0; i < 4; i++) {
                float a = Xs[ty * 4 + i][kk];
                uint64_t aa = pack2(a, a);
                fma2(acc[i][0], aa, b0);
                fma2(acc[i][1], aa, b1);
                fma2(acc[i][2], aa, b2);
                fma2(acc[i][3], aa, b3);
            }
        }
        __syncthreads();
    }

    int col = tx * 8;
#pragma unroll
    for (int i = 0; i < 4; i++) {
        int grow = row0 + ty * 4 + i;
        if (grow < M) {
            float2 p0 = unpack2(acc[i][0]);
            float2 p1 = unpack2(acc[i][1]);
            float2 p2 = unpack2(acc[i][2]);
            float2 p3 = unpack2(acc[i][3]);
            float4 v0 = make_float4(p0.x, p0.y, p1.x, p1.y);
            float4 v1 = make_float4(p2.x, p2.y, p3.x, p3.y);
            *(float4*)(g_h + (size_t)grow * 128 + col)     = v0;
            *(float4*)(g_h + (size_t)grow * 128 + col + 4) = v1;
        }
    }
}

// ---- fused: agg1 + b1 + ReLU + inline-threefry dropout + GEMM2 (128->40) -
// one warp per dst node; 8 warps / block of 256 threads.
__global__ void k_agg1_fused(const float* __restrict__ b1,
                             const float* __restrict__ W2,
                             int N) {
    __shared__ __align__(16) float Ws2[128 * NC];  // 20 KB
    __shared__ __align__(16) float b1s[128];

    for (int i = threadIdx.x; i < 128 * NC; i += blockDim.x) Ws2[i] = W2[i];
    if (threadIdx.x < 128) b1s[threadIdx.x] = b1[threadIdx.x];
    __syncthreads();

    int warp = threadIdx.x >> 5;
    int lane = threadIdx.x & 31;
    int n = blockIdx.x * (blockDim.x >> 5) + warp;
    if (n >= N) return;

    float di = g_dinv[n];
    float wself = di * di;

    // self-loop init: acc = h[n] * dinv^2
    float4 acc = ((const float4*)(g_h + (size_t)n * 128))[lane];
    acc.x *= wself; acc.y *= wself; acc.z *= wself; acc.w *= wself;

    int e  = g_rowptr[n];
    int e1 = g_rowptr[n + 1];

    // 4-way unrolled gather for MLP
    for (; e + 4 <= e1; e += 4) {
        int s0 = g_csr_src[e + 0];
        int s1 = g_csr_src[e + 1];
        int s2 = g_csr_src[e + 2];
        int s3 = g_csr_src[e + 3];
        float w0 = g_dinv[s0] * di;
        float w1 = g_dinv[s1] * di;
        float w2 = g_dinv[s2] * di;
        float w3 = g_dinv[s3] * di;
        float4 v0 = ((const float4*)(g_h + (size_t)s0 * 128))[lane];
        float4 v1 = ((const float4*)(g_h + (size_t)s1 * 128))[lane];
        float4 v2 = ((const float4*)(g_h + (size_t)s2 * 128))[lane];
        float4 v3 = ((const float4*)(g_h + (size_t)s3 * 128))[lane];
        acc.x = fmaf(v0.x, w0, acc.x); acc.y = fmaf(v0.y, w0, acc.y);
        acc.z = fmaf(v0.z, w0, acc.z); acc.w = fmaf(v0.w, w0, acc.w);
        acc.x = fmaf(v1.x, w1, acc.x); acc.y = fmaf(v1.y, w1, acc.y);
        acc.z = fmaf(v1.z, w1, acc.z); acc.w = fmaf(v1.w, w1, acc.w);
        acc.x = fmaf(v2.x, w2, acc.x); acc.y = fmaf(v2.y, w2, acc.y);
        acc.z = fmaf(v2.z, w2, acc.z); acc.w = fmaf(v2.w, w2, acc.w);
        acc.x = fmaf(v3.x, w3, acc.x); acc.y = fmaf(v3.y, w3, acc.y);
        acc.z = fmaf(v3.z, w3, acc.z); acc.w = fmaf(v3.w, w3, acc.w);
    }
    for (; e < e1; e++) {
        int s   = g_csr_src[e];
        float w = g_dinv[s] * di;
        float4 v = ((const float4*)(g_h + (size_t)s * 128))[lane];
        acc.x = fmaf(v.x, w, acc.x);
        acc.y = fmaf(v.y, w, acc.y);
        acc.z = fmaf(v.z, w, acc.z);
        acc.w = fmaf(v.w, w, acc.w);
    }

    // + b1, ReLU, dropout (inline threefry; keep -> *2, drop -> 0)
    uint32_t mi = (uint32_t)n * 128u + (uint32_t)lane * 4u;
    float4 bb = ((const float4*)b1s)[lane];
    float fc[4];
    fc[0] = fmaxf(acc.x + bb.x, 0.f) * drop_scale(mi + 0u);
    fc[1] = fmaxf(acc.y + bb.y, 0.f) * drop_scale(mi + 1u);
    fc[2] = fmaxf(acc.z + bb.z, 0.f) * drop_scale(mi + 2u);
    fc[3] = fmaxf(acc.w + bb.w, 0.f) * drop_scale(mi + 3u);

    // GEMM2 via shuffle broadcast: t2[n][c] = sum_k hd[k] * W2[k][c]
    int c1 = 32 + (lane & 7);
    float o0 = 0.f, o1 = 0.f;
#pragma unroll 4
    for (int k = 0; k < 128; k++) {
        float v = __shfl_sync(0xffffffffu, fc[k & 3], k >> 2);
        o0 = fmaf(v, Ws2[k * NC + lane], o0);
        o1 = fmaf(v, Ws2[k * NC + c1], o1);
    }

    float* tp = g_t2 + (size_t)n * NC;
    tp[lane] = o0;
    if (lane < 8) tp[c1] = o1;
}

// ---------------- agg2: out = A_norm @ t2 + b2  (width 40) ----------------
__global__ void k_agg2(const float* __restrict__ b2,
                       float* __restrict__ out,
                       int N) {
    int warp = threadIdx.x >> 5;
    int lane = threadIdx.x & 31;
    int n = blockIdx.x * (blockDim.x >> 5) + warp;
    if (n >= N) return;

    float di = g_dinv[n];
    float wself = di * di;
    int c0 = lane;
    int c1 = 32 + (lane & 7);

    const float* tn = g_t2 + (size_t)n * NC;
    float a0 = tn[c0] * wself;
    float a1 = tn[c1] * wself;

    int e  = g_rowptr[n];
    int e1 = g_rowptr[n + 1];

    for (; e + 4 <= e1; e += 4) {
        int s0 = g_csr_src[e + 0];
        int s1 = g_csr_src[e + 1];
        int s2 = g_csr_src[e + 2];
        int s3 = g_csr_src[e + 3];
        float w0 = g_dinv[s0] * di;
        float w1 = g_dinv[s1] * di;
        float w2 = g_dinv[s2] * di;
        float w3 = g_dinv[s3] * di;
        const float* t0 = g_t2 + (size_t)s0 * NC;
        const float* t1 = g_t2 + (size_t)s1 * NC;
        const float* t2 = g_t2 + (size_t)s2 * NC;
        const float* t3 = g_t2 + (size_t)s3 * NC;
        float x00 = t0[c0], x01 = t0[c1];
        float x10 = t1[c0], x11 = t1[c1];
        float x20 = t2[c0], x21 = t2[c1];
        float x30 = t3[c0], x31 = t3[c1];
        a0 = fmaf(x00, w0, a0); a1 = fmaf(x01, w0, a1);
        a0 = fmaf(x10, w1, a0); a1 = fmaf(x11, w1, a1);
        a0 = fmaf(x20, w2, a0); a1 = fmaf(x21, w2, a1);
        a0 = fmaf(x30, w3, a0); a1 = fmaf(x31, w3, a1);
    }
    for (; e < e1; e++) {
        int s   = g_csr_src[e];
        float w = g_dinv[s] * di;
        const float* ts = g_t2 + (size_t)s * NC;
        a0 = fmaf(ts[c0], w, a0);
        a1 = fmaf(ts[c1], w, a1);
    }

    out[(size_t)n * NC + c0] = a0 + b2[c0];
    if (lane < 8) out[(size_t)n * NC + c1] = a1 + b2[c1];
}

// ---------------- launch ----------------
extern "C" void kernel_launch(void* const* d_in, const int* in_sizes, int n_in,
                              void* d_out, int out_size) {
    const float* x  = (const float*)d_in[0];
    const int*   ei = (const int*)d_in[1];
    const float* W1 = (const float*)d_in[2];
    const float* b1 = (const float*)d_in[3];
    const float* W2 = (const float*)d_in[4];
    const float* b2 = (const float*)d_in[5];
    float* out = (float*)d_out;

    const int N = N_NODES;
    const int E = N_EDGES;
    const int nb = (N + 1023) / 1024;   // 98 <= 128

    k_zero  <<<(N + 255) / 256, 256>>>(N);
    k_count <<<(E + 255) / 256, 256>>>(ei, E);
    k_scan1 <<<nb, 1024>>>(N);
    k_scan2 <<<1, 128>>>(nb, N);
    k_scan3 <<<nb, 1024>>>(N);
    k_fill  <<<(E + 255) / 256, 256>>>(ei, E);
    k_gemm1 <<<(N + 63) / 64, 256>>>(x, W1, N);
    k_agg1_fused <<<(N + 7) / 8, 256>>>(b1, W2, N);
    k_agg2       <<<(N + 7) / 8, 256>>>(b2, out, N);
}

// round 6
// speedup vs baseline: 1.2040x; 1.0622x over previous
#include <cuda_runtime.h>
#include <cuda_fp16.h>
#include <stdint.h>

#define N_NODES 100000
#define N_EDGES 1600000
#define NF      128
#define NC      40

// ---------------- static scratch (no allocations allowed) ----------------
static __device__ __half g_h[(size_t)N_NODES * NF];    // 25.6 MB (fp16)
static __device__ float  g_t2[(size_t)N_NODES * NC];   // 16 MB
static __device__ float  g_dinv[N_NODES];
static __device__ int    g_cnt[N_NODES];
static __device__ int    g_rowptr[N_NODES + 1];
static __device__ int    g_cursor[N_NODES];
static __device__ int    g_csr_src[N_EDGES];           // 6.4 MB
static __device__ int    g_blocksum[128];

// ---------------- packed f32x2 helpers (Blackwell dual-rate fp32) --------
__device__ __forceinline__ uint64_t pack2(float lo, float hi) {
    uint64_t r;
    asm("mov.b64 %0, {%1, %2};" : "=l"(r) : "f"(lo), "f"(hi));
    return r;
}
__device__ __forceinline__ void fma2(uint64_t& d, uint64_t a, uint64_t b) {
    asm("fma.rn.f32x2 %0, %1, %2, %0;" : "+l"(d) : "l"(a), "l"(b));
}
__device__ __forceinline__ float2 unpack2(uint64_t v) {
    float2 f;
    asm("mov.b64 {%0, %1}, %2;" : "=f"(f.x), "=f"(f.y) : "l"(v));
    return f;
}

// ---------------- threefry2x32, key = (0, 42) ----------------
__device__ __forceinline__ uint32_t rotl32(uint32_t x, int r) {
    return (x << r) | (x >> (32 - r));
}

__device__ __forceinline__ void threefry_0_42(uint32_t& x0, uint32_t& x1) {
    const uint32_t K1 = 0u;
    const uint32_t K2 = 42u;
    const uint32_t KC = 0x1BD11BDAu ^ K1 ^ K2;  // 0x1BD11BF0
#define TF_ROUND(r) { x0 += x1; x1 = rotl32(x1, r); x1 ^= x0; }
    x0 += K1; x1 += K2;
    TF_ROUND(13) TF_ROUND(15) TF_ROUND(26) TF_ROUND(6)
    x0 += K2; x1 += KC + 1u;
    TF_ROUND(17) TF_ROUND(29) TF_ROUND(16) TF_ROUND(24)
    x0 += KC; x1 += K1 + 2u;
    TF_ROUND(13) TF_ROUND(15) TF_ROUND(26) TF_ROUND(6)
    x0 += K1; x1 += K2 + 3u;
    TF_ROUND(17) TF_ROUND(29) TF_ROUND(16) TF_ROUND(24)
    x0 += K2; x1 += KC + 4u;
    TF_ROUND(13) TF_ROUND(15) TF_ROUND(26) TF_ROUND(6)
    x0 += KC; x1 += K1 + 5u;
#undef TF_ROUND
}

// keep-mask (partitionable threefry): element i -> counter (0, i),
// bits = out0 ^ out1, keep iff MSB set. Returns 2.0f (keep) or 0.0f (drop).
__device__ __forceinline__ float drop_scale(uint32_t i) {
    uint32_t a = 0u, b = i;
    threefry_0_42(a, b);
    return ((a ^ b) >> 31) ? 2.0f : 0.0f;
}

// ---------------- small kernels: degree / CSR build ----------------
__global__ void k_zero(int N) {
    int i = blockIdx.x * blockDim.x + threadIdx.x;
    if (i < N) g_cnt[i] = 0;
}

__global__ void k_count(const int* __restrict__ ei, int E) {
    int e = blockIdx.x * blockDim.x + threadIdx.x;
    if (e < E) atomicAdd(&g_cnt[ei[E + e]], 1);
}

__global__ void k_scan1(int N) {  // blockDim = 1024: block reduce -> blocksum
    __shared__ int s[1024];
    int t = threadIdx.x;
    int i = blockIdx.x * 1024 + t;
    s[t] = (i < N) ? g_cnt[i] : 0;
    __syncthreads();
    for (int off = 512; off > 0; off >>= 1) {
        if (t < off) s[t] += s[t + off];
        __syncthreads();
    }
    if (t == 0) g_blocksum[blockIdx.x] = s[0];
}

__global__ void k_scan2(int nb, int N) {  // one 128-thread block scan
    __shared__ int s[128];
    int t = threadIdx.x;
    int v = (t < nb) ? g_blocksum[t] : 0;
    s[t] = v;
    __syncthreads();
    for (int off = 1; off < 128; off <<= 1) {
        int x = (t >= off) ? s[t - off] : 0;
        __syncthreads();
        s[t] += x;
        __syncthreads();
    }
    if (t < nb) g_blocksum[t] = s[t] - v;   // exclusive
    if (t == 127) g_rowptr[N] = s[127];     // total
}

__global__ void k_scan3(int N) {  // blockDim = 1024: in-block exclusive scan
    __shared__ int s[1024];
    int t = threadIdx.x;
    int i = blockIdx.x * 1024 + t;
    int v = (i < N) ? g_cnt[i] : 0;
    s[t] = v;
    __syncthreads();
    for (int off = 1; off < 1024; off <<= 1) {
        int x = (t >= off) ? s[t - off] : 0;
        __syncthreads();
        s[t] += x;
        __syncthreads();
    }
    if (i < N) {
        int excl = s[t] - v + g_blocksum[blockIdx.x];
        g_rowptr[i] = excl;
        g_cursor[i] = excl;
        g_dinv[i]   = rsqrtf((float)(v + 1));  // +1 self loop
    }
}

__global__ void k_fill(const int* __restrict__ ei, int E) {
    int e = blockIdx.x * blockDim.x + threadIdx.x;
    if (e < E) {
        int d   = ei[E + e];
        int pos = atomicAdd(&g_cursor[d], 1);
        g_csr_src[pos] = ei[e];
    }
}

// ---------------- GEMM1: h = x @ W1  (fp32 compute, fp16 store) ----------
// blockDim = 256, tile 64 rows x 128 cols, thread micro-tile 4x8 (4 pairs).
__global__ void k_gemm1(const float* __restrict__ x,
                        const float* __restrict__ W,
                        int M) {
    __shared__ __align__(16) float Xs[64][33];
    __shared__ __align__(16) float Ws[32][128];

    int row0 = blockIdx.x * 64;
    int tx = threadIdx.x % 16;  // 16 col groups * 8 cols
    int ty = threadIdx.x / 16;  // 16 row groups * 4 rows

    uint64_t acc[4][4];
#pragma unroll
    for (int i = 0; i < 4; i++)
#pragma unroll
        for (int j = 0; j < 4; j++) acc[i][j] = pack2(0.f, 0.f);

    for (int k0 = 0; k0 < 128; k0 += 32) {
        {
            int r  = threadIdx.x / 8;         // 0..31
            int c4 = (threadIdx.x % 8) * 4;   // 0..28
#pragma unroll
            for (int rr = r; rr < 64; rr += 32) {
                int grow = row0 + rr;
                float4 v = make_float4(0.f, 0.f, 0.f, 0.f);
                if (grow < M)
                    v = *(const float4*)(x + (size_t)grow * 128 + k0 + c4);
                Xs[rr][c4 + 0] = v.x;
                Xs[rr][c4 + 1] = v.y;
                Xs[rr][c4 + 2] = v.z;
                Xs[rr][c4 + 3] = v.w;
            }
        }
        for (int i = threadIdx.x; i < 32 * 32; i += 256) {
            int kr = i / 32;
            int cc = (i % 32) * 4;
            *(float4*)(&Ws[kr][cc]) =
                *(const float4*)(W + (size_t)(k0 + kr) * 128 + cc);
        }
        __syncthreads();

#pragma unroll
        for (int kk = 0; kk < 32; kk++) {
            const uint64_t* bp = (const uint64_t*)(&Ws[kk][tx * 8]);
            uint64_t b0 = bp[0], b1 = bp[1], b2 = bp[2], b3 = bp[3];
#pragma unroll
            for (int i = 0; i < 4; i++) {
                float a = Xs[ty * 4 + i][kk];
                uint64_t aa = pack2(a, a);
                fma2(acc[i][0], aa, b0);
                fma2(acc[i][1], aa, b1);
                fma2(acc[i][2], aa, b2);
                fma2(acc[i][3], aa, b3);
            }
        }
        __syncthreads();
    }

    int col = tx * 8;
#pragma unroll
    for (int i = 0; i < 4; i++) {
        int grow = row0 + ty * 4 + i;
        if (grow < M) {
            float2 p0 = unpack2(acc[i][0]);
            float2 p1 = unpack2(acc[i][1]);
            float2 p2 = unpack2(acc[i][2]);
            float2 p3 = unpack2(acc[i][3]);
            __half2 h0 = __float22half2_rn(p0);
            __half2 h1 = __float22half2_rn(p1);
            __half2 h2 = __float22half2_rn(p2);
            __half2 h3 = __float22half2_rn(p3);
            uint4 pkt;
            pkt.x = *(uint32_t*)&h0;
            pkt.y = *(uint32_t*)&h1;
            pkt.z = *(uint32_t*)&h2;
            pkt.w = *(uint32_t*)&h3;
            *(uint4*)(g_h + (size_t)grow * 128 + col) = pkt;
        }
    }
}

// ---- fused: agg1 + b1 + ReLU + inline-threefry dropout + GEMM2 (128->40) -
// one warp per dst node; 8 warps / block of 256 threads.
// g_h rows are fp16: each lane loads 4 halves (8 B) per edge row.
__device__ __forceinline__ void acc_half4(float4& acc, uint2 raw, float w) {
    __half2 lo = *(__half2*)&raw.x;
    __half2 hi = *(__half2*)&raw.y;
    float2 f0 = __half22float2(lo);
    float2 f1 = __half22float2(hi);
    acc.x = fmaf(f0.x, w, acc.x);
    acc.y = fmaf(f0.y, w, acc.y);
    acc.z = fmaf(f1.x, w, acc.z);
    acc.w = fmaf(f1.y, w, acc.w);
}

__global__ void k_agg1_fused(const float* __restrict__ b1,
                             const float* __restrict__ W2,
                             int N) {
    __shared__ __align__(16) float Ws2[128 * NC];  // 20 KB
    __shared__ __align__(16) float b1s[128];

    for (int i = threadIdx.x; i < 128 * NC; i += blockDim.x) Ws2[i] = W2[i];
    if (threadIdx.x < 128) b1s[threadIdx.x] = b1[threadIdx.x];
    __syncthreads();

    int warp = threadIdx.x >> 5;
    int lane = threadIdx.x & 31;
    int n = blockIdx.x * (blockDim.x >> 5) + warp;
    if (n >= N) return;

    float di = g_dinv[n];
    float wself = di * di;

    float4 acc = make_float4(0.f, 0.f, 0.f, 0.f);
    {   // self-loop: acc = h[n] * dinv^2
        uint2 raw = ((const uint2*)(g_h + (size_t)n * 128))[lane];
        acc_half4(acc, raw, wself);
    }

    int e  = g_rowptr[n];
    int e1 = g_rowptr[n + 1];

    // 8-way unrolled gather for MLP
    for (; e + 8 <= e1; e += 8) {
        int   si[8];
        float wi[8];
        uint2 vi[8];
#pragma unroll
        for (int u = 0; u < 8; u++) si[u] = g_csr_src[e + u];
#pragma unroll
        for (int u = 0; u < 8; u++) wi[u] = g_dinv[si[u]] * di;
#pragma unroll
        for (int u = 0; u < 8; u++)
            vi[u] = ((const uint2*)(g_h + (size_t)si[u] * 128))[lane];
#pragma unroll
        for (int u = 0; u < 8; u++) acc_half4(acc, vi[u], wi[u]);
    }
    for (; e < e1; e++) {
        int s   = g_csr_src[e];
        float w = g_dinv[s] * di;
        uint2 raw = ((const uint2*)(g_h + (size_t)s * 128))[lane];
        acc_half4(acc, raw, w);
    }

    // + b1, ReLU, dropout (inline threefry; keep -> *2, drop -> 0)
    uint32_t mi = (uint32_t)n * 128u + (uint32_t)lane * 4u;
    float4 bb = ((const float4*)b1s)[lane];
    float fc[4];
    fc[0] = fmaxf(acc.x + bb.x, 0.f) * drop_scale(mi + 0u);
    fc[1] = fmaxf(acc.y + bb.y, 0.f) * drop_scale(mi + 1u);
    fc[2] = fmaxf(acc.z + bb.z, 0.f) * drop_scale(mi + 2u);
    fc[3] = fmaxf(acc.w + bb.w, 0.f) * drop_scale(mi + 3u);

    // GEMM2 via shuffle broadcast: t2[n][c] = sum_k hd[k] * W2[k][c]
    int c1 = 32 + (lane & 7);
    float o0 = 0.f, o1 = 0.f;
#pragma unroll 4
    for (int k = 0; k < 128; k++) {
        float v = __shfl_sync(0xffffffffu, fc[k & 3], k >> 2);
        o0 = fmaf(v, Ws2[k * NC + lane], o0);
        o1 = fmaf(v, Ws2[k * NC + c1], o1);
    }

    float* tp = g_t2 + (size_t)n * NC;
    tp[lane] = o0;
    if (lane < 8) tp[c1] = o1;
}

// ---------------- agg2: out = A_norm @ t2 + b2  (width 40) ----------------
__global__ void k_agg2(const float* __restrict__ b2,
                       float* __restrict__ out,
                       int N) {
    int warp = threadIdx.x >> 5;
    int lane = threadIdx.x & 31;
    int n = blockIdx.x * (blockDim.x >> 5) + warp;
    if (n >= N) return;

    float di = g_dinv[n];
    float wself = di * di;
    int c0 = lane;
    int c1 = 32 + (lane & 7);

    const float* tn = g_t2 + (size_t)n * NC;
    float a0 = tn[c0] * wself;
    float a1 = tn[c1] * wself;

    int e  = g_rowptr[n];
    int e1 = g_rowptr[n + 1];

    for (; e + 4 <= e1; e += 4) {
        int s0 = g_csr_src[e + 0];
        int s1 = g_csr_src[e + 1];
        int s2 = g_csr_src[e + 2];
        int s3 = g_csr_src[e + 3];
        float w0 = g_dinv[s0] * di;
        float w1 = g_dinv[s1] * di;
        float w2 = g_dinv[s2] * di;
        float w3 = g_dinv[s3] * di;
        const float* t0 = g_t2 + (size_t)s0 * NC;
        const float* t1 = g_t2 + (size_t)s1 * NC;
        const float* t2 = g_t2 + (size_t)s2 * NC;
        const float* t3 = g_t2 + (size_t)s3 * NC;
        float x00 = t0[c0], x01 = t0[c1];
        float x10 = t1[c0], x11 = t1[c1];
        float x20 = t2[c0], x21 = t2[c1];
        float x30 = t3[c0], x31 = t3[c1];
        a0 = fmaf(x00, w0, a0); a1 = fmaf(x01, w0, a1);
        a0 = fmaf(x10, w1, a0); a1 = fmaf(x11, w1, a1);
        a0 = fmaf(x20, w2, a0); a1 = fmaf(x21, w2, a1);
        a0 = fmaf(x30, w3, a0); a1 = fmaf(x31, w3, a1);
    }
    for (; e < e1; e++) {
        int s   = g_csr_src[e];
        float w = g_dinv[s] * di;
        const float* ts = g_t2 + (size_t)s * NC;
        a0 = fmaf(ts[c0], w, a0);
        a1 = fmaf(ts[c1], w, a1);
    }

    out[(size_t)n * NC + c0] = a0 + b2[c0];
    if (lane < 8) out[(size_t)n * NC + c1] = a1 + b2[c1];
}

// ---------------- launch ----------------
extern "C" void kernel_launch(void* const* d_in, const int* in_sizes, int n_in,
                              void* d_out, int out_size) {
    const float* x  = (const float*)d_in[0];
    const int*   ei = (const int*)d_in[1];
    const float* W1 = (const float*)d_in[2];
    const float* b1 = (const float*)d_in[3];
    const float* W2 = (const float*)d_in[4];
    const float* b2 = (const float*)d_in[5];
    float* out = (float*)d_out;

    const int N = N_NODES;
    const int E = N_EDGES;
    const int nb = (N + 1023) / 1024;   // 98 <= 128

    k_zero  <<<(N + 255) / 256, 256>>>(N);
    k_count <<<(E + 255) / 256, 256>>>(ei, E);
    k_scan1 <<<nb, 1024>>>(N);
    k_scan2 <<<1, 128>>>(nb, N);
    k_scan3 <<<nb, 1024>>>(N);
    k_fill  <<<(E + 255) / 256, 256>>>(ei, E);
    k_gemm1 <<<(N + 63) / 64, 256>>>(x, W1, N);
    k_agg1_fused <<<(N + 7) / 8, 256>>>(b1, W2, N);
    k_agg2       <<<(N + 7) / 8, 256>>>(b2, out, N);
}

// round 7
// speedup vs baseline: 1.4287x; 1.1866x over previous
#include <cuda_runtime.h>
#include <cuda_fp16.h>
#include <stdint.h>

#define N_NODES 100000
#define N_EDGES 1600000
#define NF      128
#define NC      40

// ---------------- static scratch (no allocations allowed) ----------------
static __device__ __half g_h [(size_t)N_NODES * NF];        // 25.6 MB
static __device__ __half g_hd[(size_t)N_NODES * NF];        // 25.6 MB
static __device__ __half g_t2[(size_t)N_NODES * NC + 64];   // 8 MB (+pad)
static __device__ float  g_dinv[N_NODES];
static __device__ int    g_cnt[N_NODES];
static __device__ int    g_rowptr[N_NODES + 1];
static __device__ int    g_cursor[N_NODES];
static __device__ int    g_csr_src[N_EDGES];                // 6.4 MB
static __device__ int    g_blocksum[128];

// ---------------- packed f32x2 helpers (Blackwell dual-rate fp32) --------
__device__ __forceinline__ uint64_t pack2(float lo, float hi) {
    uint64_t r;
    asm("mov.b64 %0, {%1, %2};" : "=l"(r) : "f"(lo), "f"(hi));
    return r;
}
__device__ __forceinline__ void fma2(uint64_t& d, uint64_t a, uint64_t b) {
    asm("fma.rn.f32x2 %0, %1, %2, %0;" : "+l"(d) : "l"(a), "l"(b));
}
__device__ __forceinline__ float2 unpack2(uint64_t v) {
    float2 f;
    asm("mov.b64 {%0, %1}, %2;" : "=f"(f.x), "=f"(f.y) : "l"(v));
    return f;
}

// ---------------- threefry2x32, key = (0, 42) ----------------
__device__ __forceinline__ uint32_t rotl32(uint32_t x, int r) {
    return (x << r) | (x >> (32 - r));
}

__device__ __forceinline__ void threefry_0_42(uint32_t& x0, uint32_t& x1) {
    const uint32_t K1 = 0u;
    const uint32_t K2 = 42u;
    const uint32_t KC = 0x1BD11BDAu ^ K1 ^ K2;
#define TF_ROUND(r) { x0 += x1; x1 = rotl32(x1, r); x1 ^= x0; }
    x0 += K1; x1 += K2;
    TF_ROUND(13) TF_ROUND(15) TF_ROUND(26) TF_ROUND(6)
    x0 += K2; x1 += KC + 1u;
    TF_ROUND(17) TF_ROUND(29) TF_ROUND(16) TF_ROUND(24)
    x0 += KC; x1 += K1 + 2u;
    TF_ROUND(13) TF_ROUND(15) TF_ROUND(26) TF_ROUND(6)
    x0 += K1; x1 += K2 + 3u;
    TF_ROUND(17) TF_ROUND(29) TF_ROUND(16) TF_ROUND(24)
    x0 += K2; x1 += KC + 4u;
    TF_ROUND(13) TF_ROUND(15) TF_ROUND(26) TF_ROUND(6)
    x0 += KC; x1 += K1 + 5u;
#undef TF_ROUND
}

__device__ __forceinline__ float drop_scale(uint32_t i) {
    uint32_t a = 0u, b = i;
    threefry_0_42(a, b);
    return ((a ^ b) >> 31) ? 2.0f : 0.0f;
}

// ---------------- small kernels: degree / CSR build ----------------
__global__ void k_zero(int N) {
    int i = blockIdx.x * blockDim.x + threadIdx.x;
    if (i < N) g_cnt[i] = 0;
}

__global__ void k_count(const int* __restrict__ ei, int E) {
    int e = blockIdx.x * blockDim.x + threadIdx.x;
    if (e < E) atomicAdd(&g_cnt[ei[E + e]], 1);
}

__global__ void k_scan1(int N) {
    __shared__ int s[1024];
    int t = threadIdx.x;
    int i = blockIdx.x * 1024 + t;
    s[t] = (i < N) ? g_cnt[i] : 0;
    __syncthreads();
    for (int off = 512; off > 0; off >>= 1) {
        if (t < off) s[t] += s[t + off];
        __syncthreads();
    }
    if (t == 0) g_blocksum[blockIdx.x] = s[0];
}

__global__ void k_scan2(int nb, int N) {
    __shared__ int s[128];
    int t = threadIdx.x;
    int v = (t < nb) ? g_blocksum[t] : 0;
    s[t] = v;
    __syncthreads();
    for (int off = 1; off < 128; off <<= 1) {
        int x = (t >= off) ? s[t - off] : 0;
        __syncthreads();
        s[t] += x;
        __syncthreads();
    }
    if (t < nb) g_blocksum[t] = s[t] - v;
    if (t == 127) g_rowptr[N] = s[127];
}

__global__ void k_scan3(int N) {
    __shared__ int s[1024];
    int t = threadIdx.x;
    int i = blockIdx.x * 1024 + t;
    int v = (i < N) ? g_cnt[i] : 0;
    s[t] = v;
    __syncthreads();
    for (int off = 1; off < 1024; off <<= 1) {
        int x = (t >= off) ? s[t - off] : 0;
        __syncthreads();
        s[t] += x;
        __syncthreads();
    }
    if (i < N) {
        int excl = s[t] - v + g_blocksum[blockIdx.x];
        g_rowptr[i] = excl;
        g_cursor[i] = excl;
        g_dinv[i]   = rsqrtf((float)(v + 1));
    }
}

__global__ void k_fill(const int* __restrict__ ei, int E) {
    int e = blockIdx.x * blockDim.x + threadIdx.x;
    if (e < E) {
        int d   = ei[E + e];
        int pos = atomicAdd(&g_cursor[d], 1);
        g_csr_src[pos] = ei[e];
    }
}

// ---------------- GEMM1: h = x @ W1  (fp32 compute, fp16 store) ----------
__global__ void k_gemm1(const float* __restrict__ x,
                        const float* __restrict__ W,
                        int M) {
    __shared__ __align__(16) float Xs[64][33];
    __shared__ __align__(16) float Ws[32][128];

    int row0 = blockIdx.x * 64;
    int tx = threadIdx.x % 16;
    int ty = threadIdx.x / 16;

    uint64_t acc[4][4];
#pragma unroll
    for (int i = 0; i < 4; i++)
#pragma unroll
        for (int j = 0; j < 4; j++) acc[i][j] = pack2(0.f, 0.f);

    for (int k0 = 0; k0 < 128; k0 += 32) {
        {
            int r  = threadIdx.x / 8;
            int c4 = (threadIdx.x % 8) * 4;
#pragma unroll
            for (int rr = r; rr < 64; rr += 32) {
                int grow = row0 + rr;
                float4 v = make_float4(0.f, 0.f, 0.f, 0.f);
                if (grow < M)
                    v = *(const float4*)(x + (size_t)grow * 128 + k0 + c4);
                Xs[rr][c4 + 0] = v.x;
                Xs[rr][c4 + 1] = v.y;
                Xs[rr][c4 + 2] = v.z;
                Xs[rr][c4 + 3] = v.w;
            }
        }
        for (int i = threadIdx.x; i < 32 * 32; i += 256) {
            int kr = i / 32;
            int cc = (i % 32) * 4;
            *(float4*)(&Ws[kr][cc]) =
                *(const float4*)(W + (size_t)(k0 + kr) * 128 + cc);
        }
        __syncthreads();

#pragma unroll
        for (int kk = 0; kk < 32; kk++) {
            const uint64_t* bp = (const uint64_t*)(&Ws[kk][tx * 8]);
            uint64_t b0 = bp[0], b1 = bp[1], b2 = bp[2], b3 = bp[3];
#pragma unroll
            for (int i = 0; i < 4; i++) {
                float a = Xs[ty * 4 + i][kk];
                uint64_t aa = pack2(a, a);
                fma2(acc[i][0], aa, b0);
                fma2(acc[i][1], aa, b1);
                fma2(acc[i][2], aa, b2);
                fma2(acc[i][3], aa, b3);
            }
        }
        __syncthreads();
    }

    int col = tx * 8;
#pragma unroll
    for (int i = 0; i < 4; i++) {
        int grow = row0 + ty * 4 + i;
        if (grow < M) {
            float2 p0 = unpack2(acc[i][0]);
            float2 p1 = unpack2(acc[i][1]);
            float2 p2 = unpack2(acc[i][2]);
            float2 p3 = unpack2(acc[i][3]);
            __half2 h0 = __float22half2_rn(p0);
            __half2 h1 = __float22half2_rn(p1);
            __half2 h2 = __float22half2_rn(p2);
            __half2 h3 = __float22half2_rn(p3);
            uint4 pkt;
            pkt.x = *(uint32_t*)&h0;
            pkt.y = *(uint32_t*)&h1;
            pkt.z = *(uint32_t*)&h2;
            pkt.w = *(uint32_t*)&h3;
            *(uint4*)(g_h + (size_t)grow * 128 + col) = pkt;
        }
    }
}

// ---- agg1: hd = dropout(relu(A_norm @ h + b1)), stored fp16 ----
__device__ __forceinline__ void acc_half4(float4& acc, uint2 raw, float w) {
    __half2 lo = *(__half2*)&raw.x;
    __half2 hi = *(__half2*)&raw.y;
    float2 f0 = __half22float2(lo);
    float2 f1 = __half22float2(hi);
    acc.x = fmaf(f0.x, w, acc.x);
    acc.y = fmaf(f0.y, w, acc.y);
    acc.z = fmaf(f1.x, w, acc.z);
    acc.w = fmaf(f1.y, w, acc.w);
}

__global__ void k_agg1(const float* __restrict__ b1, int N) {
    int warp = threadIdx.x >> 5;
    int lane = threadIdx.x & 31;
    int n = blockIdx.x * (blockDim.x >> 5) + warp;
    if (n >= N) return;

    float di = g_dinv[n];
    float wself = di * di;

    float4 acc = make_float4(0.f, 0.f, 0.f, 0.f);
    {
        uint2 raw = ((const uint2*)(g_h + (size_t)n * 128))[lane];
        acc_half4(acc, raw, wself);
    }

    int e  = g_rowptr[n];
    int e1 = g_rowptr[n + 1];

    for (; e + 8 <= e1; e += 8) {
        int   si[8];
        float wi[8];
        uint2 vi[8];
#pragma unroll
        for (int u = 0; u < 8; u++) si[u] = g_csr_src[e + u];
#pragma unroll
        for (int u = 0; u < 8; u++) wi[u] = g_dinv[si[u]] * di;
#pragma unroll
        for (int u = 0; u < 8; u++)
            vi[u] = ((const uint2*)(g_h + (size_t)si[u] * 128))[lane];
#pragma unroll
        for (int u = 0; u < 8; u++) acc_half4(acc, vi[u], wi[u]);
    }
    for (; e < e1; e++) {
        int s   = g_csr_src[e];
        float w = g_dinv[s] * di;
        uint2 raw = ((const uint2*)(g_h + (size_t)s * 128))[lane];
        acc_half4(acc, raw, w);
    }

    // + b1, ReLU, dropout; store fp16
    uint32_t mi = (uint32_t)n * 128u + (uint32_t)lane * 4u;
    float4 bb = ((const float4*)b1)[lane];
    float f0 = fmaxf(acc.x + bb.x, 0.f) * drop_scale(mi + 0u);
    float f1 = fmaxf(acc.y + bb.y, 0.f) * drop_scale(mi + 1u);
    float f2 = fmaxf(acc.z + bb.z, 0.f) * drop_scale(mi + 2u);
    float f3 = fmaxf(acc.w + bb.w, 0.f) * drop_scale(mi + 3u);

    __half2 h0 = __floats2half2_rn(f0, f1);
    __half2 h1 = __floats2half2_rn(f2, f3);
    uint2 pkt;
    pkt.x = *(uint32_t*)&h0;
    pkt.y = *(uint32_t*)&h1;
    ((uint2*)(g_hd + (size_t)n * 128))[lane] = pkt;
}

// ---------------- GEMM2: t2 = hd @ W2  (fp16 in, fp32 acc, fp16 out) -----
// blockDim = 320 (10 warps). Warp w owns 4 output cols (w*4). Lane owns
// 2 rows (2*lane, 2*lane+1) of a 64-row tile. hd staged transposed in smem.
#define G2_ROWS 64
__global__ __launch_bounds__(320) void k_gemm2(const float* __restrict__ W2,
                                               int M) {
    __shared__ __align__(16) __half Xs[128 * G2_ROWS];   // Xs[k*64+m], 16 KB
    __shared__ __align__(16) float  Ws[128 * NC];        // 20 KB

    int tid  = threadIdx.x;
    int row0 = blockIdx.x * G2_ROWS;

    // stage W2 (128x40 f32)
    for (int i = tid; i < 128 * NC / 4; i += 320)
        ((float4*)Ws)[i] = ((const float4*)W2)[i];

    // stage hd tile transposed: Xs[k][m] = hd[row0+m][k]
    for (int i = tid; i < G2_ROWS * 16; i += 320) {
        int m  = i / 16;
        int k8 = (i % 16) * 8;
        uint4 v = make_uint4(0u, 0u, 0u, 0u);
        if (row0 + m < M)
            v = ((const uint4*)(g_hd + (size_t)(row0 + m) * 128))[i % 16];
        __half* hp = (__half*)&v;
#pragma unroll
        for (int j = 0; j < 8; j++) Xs[(k8 + j) * G2_ROWS + m] = hp[j];
    }
    __syncthreads();

    int w    = tid >> 5;         // 0..9 -> col quad
    int lane = tid & 31;
    int c0   = w * 4;

    uint64_t a00 = pack2(0.f, 0.f), a01 = a00;   // row 2*lane
    uint64_t a10 = a00, a11 = a00;               // row 2*lane+1

#pragma unroll 4
    for (int k = 0; k < 128; k++) {
        __half2 xv = *(__half2*)&Xs[k * G2_ROWS + 2 * lane];
        float2  xf = __half22float2(xv);
        float4  wv = *(const float4*)&Ws[k * NC + c0];   // broadcast
        uint64_t w01 = pack2(wv.x, wv.y);
        uint64_t w23 = pack2(wv.z, wv.w);
        uint64_t x0  = pack2(xf.x, xf.x);
        uint64_t x1  = pack2(xf.y, xf.y);
        fma2(a00, x0, w01); fma2(a01, x0, w23);
        fma2(a10, x1, w01); fma2(a11, x1, w23);
    }

    int m0 = row0 + 2 * lane;
    if (m0 < M) {
        float2 p0 = unpack2(a00), p1 = unpack2(a01);
        __half2 h0 = __float22half2_rn(p0);
        __half2 h1 = __float22half2_rn(p1);
        uint2 pkt; pkt.x = *(uint32_t*)&h0; pkt.y = *(uint32_t*)&h1;
        *(uint2*)(g_t2 + (size_t)m0 * NC + c0) = pkt;
    }
    if (m0 + 1 < M) {
        float2 p0 = unpack2(a10), p1 = unpack2(a11);
        __half2 h0 = __float22half2_rn(p0);
        __half2 h1 = __float22half2_rn(p1);
        uint2 pkt; pkt.x = *(uint32_t*)&h0; pkt.y = *(uint32_t*)&h1;
        *(uint2*)(g_t2 + (size_t)(m0 + 1) * NC + c0) = pkt;
    }
}

// ---------------- agg2: out = A_norm @ t2 + b2  (t2 fp16, out fp32) ------
// lanes 0..19 each own 2 cols (half2); lanes 20..31 idle on data.
__global__ void k_agg2(const float* __restrict__ b2,
                       float* __restrict__ out,
                       int N) {
    int warp = threadIdx.x >> 5;
    int lane = threadIdx.x & 31;
    int n = blockIdx.x * (blockDim.x >> 5) + warp;
    if (n >= N) return;

    bool active = lane < 20;
    float di = g_dinv[n];
    float wself = di * di;

    float2 a = make_float2(0.f, 0.f);
    if (active) {
        __half2 v = ((const __half2*)(g_t2 + (size_t)n * NC))[lane];
        float2 f = __half22float2(v);
        a.x = f.x * wself;
        a.y = f.y * wself;
    }

    int e  = g_rowptr[n];
    int e1 = g_rowptr[n + 1];

    for (; e + 8 <= e1; e += 8) {
        int     si[8];
        float   wi[8];
        __half2 vi[8];
#pragma unroll
        for (int u = 0; u < 8; u++) si[u] = g_csr_src[e + u];
#pragma unroll
        for (int u = 0; u < 8; u++) wi[u] = g_dinv[si[u]] * di;
#pragma unroll
        for (int u = 0; u < 8; u++)
            vi[u] = active
                  ? ((const __half2*)(g_t2 + (size_t)si[u] * NC))[lane]
                  : __half2();
#pragma unroll
        for (int u = 0; u < 8; u++) {
            float2 f = __half22float2(vi[u]);
            a.x = fmaf(f.x, wi[u], a.x);
            a.y = fmaf(f.y, wi[u], a.y);
        }
    }
    for (; e < e1; e++) {
        int s   = g_csr_src[e];
        float w = g_dinv[s] * di;
        if (active) {
            __half2 v = ((const __half2*)(g_t2 + (size_t)s * NC))[lane];
            float2 f = __half22float2(v);
            a.x = fmaf(f.x, w, a.x);
            a.y = fmaf(f.y, w, a.y);
        }
    }

    if (active) {
        float2 bv = ((const float2*)b2)[lane];
        float2 o = make_float2(a.x + bv.x, a.y + bv.y);
        *(float2*)(out + (size_t)n * NC + 2 * lane) = o;
    }
}

// ---------------- launch ----------------
extern "C" void kernel_launch(void* const* d_in, const int* in_sizes, int n_in,
                              void* d_out, int out_size) {
    const float* x  = (const float*)d_in[0];
    const int*   ei = (const int*)d_in[1];
    const float* W1 = (const float*)d_in[2];
    const float* b1 = (const float*)d_in[3];
    const float* W2 = (const float*)d_in[4];
    const float* b2 = (const float*)d_in[5];
    float* out = (float*)d_out;

    const int N = N_NODES;
    const int E = N_EDGES;
    const int nb = (N + 1023) / 1024;

    k_zero  <<<(N + 255) / 256, 256>>>(N);
    k_count <<<(E + 255) / 256, 256>>>(ei, E);
    k_scan1 <<<nb, 1024>>>(N);
    k_scan2 <<<1, 128>>>(nb, N);
    k_scan3 <<<nb, 1024>>>(N);
    k_fill  <<<(E + 255) / 256, 256>>>(ei, E);
    k_gemm1 <<<(N + 63) / 64, 256>>>(x, W1, N);
    k_agg1  <<<(N + 7) / 8, 256>>>(b1, N);
    k_gemm2 <<<(N + G2_ROWS - 1) / G2_ROWS, 320>>>(W2, N);
    k_agg2  <<<(N + 7) / 8, 256>>>(b2, out, N);
}

// round 8
// speedup vs baseline: 1.8337x; 1.2835x over previous
#include <cuda_runtime.h>
#include <cuda_fp16.h>
#include <stdint.h>

#define N_NODES 100000
#define N_EDGES 1600000
#define NF      128
#define NC      40

// ---------------- static scratch (no allocations allowed) ----------------
static __device__ __half g_h [(size_t)N_NODES * NF];        // 25.6 MB
static __device__ __half g_hd[(size_t)N_NODES * NF];        // 25.6 MB
static __device__ __half g_t2[(size_t)N_NODES * NC + 64];   // 8 MB (+pad)
static __device__ float  g_dinv[N_NODES];
static __device__ int    g_cnt[N_NODES];
static __device__ int    g_rowptr[N_NODES + 1];
static __device__ int    g_cursor[N_NODES];
static __device__ int    g_csr_src[N_EDGES];                // 6.4 MB
static __device__ int    g_blocksum[128];

// ---------------- packed f32x2 helpers (Blackwell dual-rate fp32) --------
__device__ __forceinline__ uint64_t pack2(float lo, float hi) {
    uint64_t r;
    asm("mov.b64 %0, {%1, %2};" : "=l"(r) : "f"(lo), "f"(hi));
    return r;
}
__device__ __forceinline__ void fma2(uint64_t& d, uint64_t a, uint64_t b) {
    asm("fma.rn.f32x2 %0, %1, %2, %0;" : "+l"(d) : "l"(a), "l"(b));
}
__device__ __forceinline__ float2 unpack2(uint64_t v) {
    float2 f;
    asm("mov.b64 {%0, %1}, %2;" : "=f"(f.x), "=f"(f.y) : "l"(v));
    return f;
}

// ---------------- threefry2x32, key = (0, 42) ----------------
__device__ __forceinline__ uint32_t rotl32(uint32_t x, int r) {
    return (x << r) | (x >> (32 - r));
}

__device__ __forceinline__ void threefry_0_42(uint32_t& x0, uint32_t& x1) {
    const uint32_t K1 = 0u;
    const uint32_t K2 = 42u;
    const uint32_t KC = 0x1BD11BDAu ^ K1 ^ K2;
#define TF_ROUND(r) { x0 += x1; x1 = rotl32(x1, r); x1 ^= x0; }
    x0 += K1; x1 += K2;
    TF_ROUND(13) TF_ROUND(15) TF_ROUND(26) TF_ROUND(6)
    x0 += K2; x1 += KC + 1u;
    TF_ROUND(17) TF_ROUND(29) TF_ROUND(16) TF_ROUND(24)
    x0 += KC; x1 += K1 + 2u;
    TF_ROUND(13) TF_ROUND(15) TF_ROUND(26) TF_ROUND(6)
    x0 += K1; x1 += K2 + 3u;
    TF_ROUND(17) TF_ROUND(29) TF_ROUND(16) TF_ROUND(24)
    x0 += K2; x1 += KC + 4u;
    TF_ROUND(13) TF_ROUND(15) TF_ROUND(26) TF_ROUND(6)
    x0 += KC; x1 += K1 + 5u;
#undef TF_ROUND
}

__device__ __forceinline__ float drop_scale(uint32_t i) {
    uint32_t a = 0u, b = i;
    threefry_0_42(a, b);
    return ((a ^ b) >> 31) ? 2.0f : 0.0f;
}

// ---------------- small kernels: degree / CSR build ----------------
__global__ void k_zero(int N) {
    int i = blockIdx.x * blockDim.x + threadIdx.x;
    if (i < N) g_cnt[i] = 0;
}

__global__ void k_count(const int* __restrict__ ei, int E) {
    int e = blockIdx.x * blockDim.x + threadIdx.x;
    if (e < E) atomicAdd(&g_cnt[ei[E + e]], 1);
}

__global__ void k_scan1(int N) {
    __shared__ int s[1024];
    int t = threadIdx.x;
    int i = blockIdx.x * 1024 + t;
    s[t] = (i < N) ? g_cnt[i] : 0;
    __syncthreads();
    for (int off = 512; off > 0; off >>= 1) {
        if (t < off) s[t] += s[t + off];
        __syncthreads();
    }
    if (t == 0) g_blocksum[blockIdx.x] = s[0];
}

__global__ void k_scan2(int nb, int N) {
    __shared__ int s[128];
    int t = threadIdx.x;
    int v = (t < nb) ? g_blocksum[t] : 0;
    s[t] = v;
    __syncthreads();
    for (int off = 1; off < 128; off <<= 1) {
        int x = (t >= off) ? s[t - off] : 0;
        __syncthreads();
        s[t] += x;
        __syncthreads();
    }
    if (t < nb) g_blocksum[t] = s[t] - v;
    if (t == 127) g_rowptr[N] = s[127];
}

__global__ void k_scan3(int N) {
    __shared__ int s[1024];
    int t = threadIdx.x;
    int i = blockIdx.x * 1024 + t;
    int v = (i < N) ? g_cnt[i] : 0;
    s[t] = v;
    __syncthreads();
    for (int off = 1; off < 1024; off <<= 1) {
        int x = (t >= off) ? s[t - off] : 0;
        __syncthreads();
        s[t] += x;
        __syncthreads();
    }
    if (i < N) {
        int excl = s[t] - v + g_blocksum[blockIdx.x];
        g_rowptr[i] = excl;
        g_cursor[i] = excl;
        g_dinv[i]   = rsqrtf((float)(v + 1));
    }
}

__global__ void k_fill(const int* __restrict__ ei, int E) {
    int e = blockIdx.x * blockDim.x + threadIdx.x;
    if (e < E) {
        int d   = ei[E + e];
        int pos = atomicAdd(&g_cursor[d], 1);
        g_csr_src[pos] = ei[e];
    }
}

// ---------------- GEMM1: h = x @ W1, fp16 tensor cores (mma.sync) --------
// Block = 256 threads (8 warps), tile 128 rows x 128 cols, K=128.
// W1 transposed+converted once to smem Wt[n][k]; x converted per 16-k slab.
#define WT_PAD 136   // halves per Wt row (conflict-free B-frag reads)
#define AS_PAD 24    // halves per As row

__device__ __forceinline__ void mma16816(float c[4],
                                         uint32_t a0, uint32_t a1,
                                         uint32_t a2, uint32_t a3,
                                         uint32_t b0, uint32_t b1) {
    asm volatile(
        "mma.sync.aligned.m16n8k16.row.col.f32.f16.f16.f32 "
        "{%0,%1,%2,%3}, {%4,%5,%6,%7}, {%8,%9}, {%0,%1,%2,%3};"
        : "+f"(c[0]), "+f"(c[1]), "+f"(c[2]), "+f"(c[3])
        : "r"(a0), "r"(a1), "r"(a2), "r"(a3), "r"(b0), "r"(b1));
}

__global__ __launch_bounds__(256) void k_gemm1(const float* __restrict__ x,
                                               const float* __restrict__ W,
                                               int M) {
    __shared__ __align__(16) __half Wt[128 * WT_PAD];  // ~34 KB
    __shared__ __align__(16) __half As[128 * AS_PAD];  // ~6 KB

    int tid  = threadIdx.x;
    int row0 = blockIdx.x * 128;

    // stage Wt[n][k] = (half)W[k][n]; coalesced loads, modest smem conflicts
    for (int i = tid; i < 128 * 32; i += 256) {
        int n  = i & 127;          // 0..127
        int kg = i >> 7;           // 0..31 -> k = 4*kg..4*kg+3
#pragma unroll
        for (int j = 0; j < 4; j++) {
            int k = 4 * kg + j;
            Wt[n * WT_PAD + k] = __float2half(W[(size_t)k * 128 + n]);
        }
    }

    int warp = tid >> 5;
    int lane = tid & 31;
    int g = lane >> 2;     // 0..7
    int t = lane & 3;      // 0..3
    int m0 = warp * 16;

    float acc[16][4];
#pragma unroll
    for (int nt = 0; nt < 16; nt++)
#pragma unroll
        for (int j = 0; j < 4; j++) acc[nt][j] = 0.f;

    for (int k0 = 0; k0 < 128; k0 += 16) {
        __syncthreads();
        // stage As[row][kc] = (half)x[row0+row][k0+kc], 128x16
        for (int i = tid; i < 128 * 4; i += 256) {
            int row = i >> 2;
            int c4  = (i & 3) * 4;
            int grow = row0 + row;
            float4 v = make_float4(0.f, 0.f, 0.f, 0.f);
            if (grow < M)
                v = *(const float4*)(x + (size_t)grow * 128 + k0 + c4);
            __half* ap = &As[row * AS_PAD + c4];
            ap[0] = __float2half(v.x);
            ap[1] = __float2half(v.y);
            ap[2] = __float2half(v.z);
            ap[3] = __float2half(v.w);
        }
        __syncthreads();

        uint32_t a0 = *(uint32_t*)&As[(m0 + g)     * AS_PAD + 2 * t];
        uint32_t a1 = *(uint32_t*)&As[(m0 + g + 8) * AS_PAD + 2 * t];
        uint32_t a2 = *(uint32_t*)&As[(m0 + g)     * AS_PAD + 2 * t + 8];
        uint32_t a3 = *(uint32_t*)&As[(m0 + g + 8) * AS_PAD + 2 * t + 8];

#pragma unroll
        for (int nt = 0; nt < 16; nt++) {
            const __half* wp = &Wt[(nt * 8 + g) * WT_PAD + k0 + 2 * t];
            uint32_t b0 = *(uint32_t*)(wp);
            uint32_t b1 = *(uint32_t*)(wp + 8);
            mma16816(acc[nt], a0, a1, a2, a3, b0, b1);
        }
    }

    // epilogue: store fp16 h
    int r_lo = row0 + m0 + g;
    int r_hi = r_lo + 8;
#pragma unroll
    for (int nt = 0; nt < 16; nt++) {
        int col = nt * 8 + 2 * t;
        if (r_lo < M) {
            __half2 hv = __floats2half2_rn(acc[nt][0], acc[nt][1]);
            *(uint32_t*)(g_h + (size_t)r_lo * 128 + col) = *(uint32_t*)&hv;
        }
        if (r_hi < M) {
            __half2 hv = __floats2half2_rn(acc[nt][2], acc[nt][3]);
            *(uint32_t*)(g_h + (size_t)r_hi * 128 + col) = *(uint32_t*)&hv;
        }
    }
}

// ---- agg1: hd = dropout(relu(A_norm @ h + b1)), stored fp16 ----
__device__ __forceinline__ void acc_half4(float4& acc, uint2 raw, float w) {
    __half2 lo = *(__half2*)&raw.x;
    __half2 hi = *(__half2*)&raw.y;
    float2 f0 = __half22float2(lo);
    float2 f1 = __half22float2(hi);
    acc.x = fmaf(f0.x, w, acc.x);
    acc.y = fmaf(f0.y, w, acc.y);
    acc.z = fmaf(f1.x, w, acc.z);
    acc.w = fmaf(f1.y, w, acc.w);
}

__global__ void k_agg1(const float* __restrict__ b1, int N) {
    int warp = threadIdx.x >> 5;
    int lane = threadIdx.x & 31;
    int n = blockIdx.x * (blockDim.x >> 5) + warp;
    if (n >= N) return;

    float di = g_dinv[n];
    float wself = di * di;

    float4 acc = make_float4(0.f, 0.f, 0.f, 0.f);
    {
        uint2 raw = ((const uint2*)(g_h + (size_t)n * 128))[lane];
        acc_half4(acc, raw, wself);
    }

    int e  = g_rowptr[n];
    int e1 = g_rowptr[n + 1];

    for (; e + 8 <= e1; e += 8) {
        int   si[8];
        float wi[8];
        uint2 vi[8];
#pragma unroll
        for (int u = 0; u < 8; u++) si[u] = g_csr_src[e + u];
#pragma unroll
        for (int u = 0; u < 8; u++) wi[u] = g_dinv[si[u]] * di;
#pragma unroll
        for (int u = 0; u < 8; u++)
            vi[u] = ((const uint2*)(g_h + (size_t)si[u] * 128))[lane];
#pragma unroll
        for (int u = 0; u < 8; u++) acc_half4(acc, vi[u], wi[u]);
    }
    for (; e < e1; e++) {
        int s   = g_csr_src[e];
        float w = g_dinv[s] * di;
        uint2 raw = ((const uint2*)(g_h + (size_t)s * 128))[lane];
        acc_half4(acc, raw, w);
    }

    uint32_t mi = (uint32_t)n * 128u + (uint32_t)lane * 4u;
    float4 bb = ((const float4*)b1)[lane];
    float f0 = fmaxf(acc.x + bb.x, 0.f) * drop_scale(mi + 0u);
    float f1 = fmaxf(acc.y + bb.y, 0.f) * drop_scale(mi + 1u);
    float f2 = fmaxf(acc.z + bb.z, 0.f) * drop_scale(mi + 2u);
    float f3 = fmaxf(acc.w + bb.w, 0.f) * drop_scale(mi + 3u);

    __half2 h0 = __floats2half2_rn(f0, f1);
    __half2 h1 = __floats2half2_rn(f2, f3);
    uint2 pkt;
    pkt.x = *(uint32_t*)&h0;
    pkt.y = *(uint32_t*)&h1;
    ((uint2*)(g_hd + (size_t)n * 128))[lane] = pkt;
}

// ---------------- GEMM2: t2 = hd @ W2  (fp16 in, fp32 acc, fp16 out) -----
#define G2_ROWS 64
__global__ __launch_bounds__(320) void k_gemm2(const float* __restrict__ W2,
                                               int M) {
    __shared__ __align__(16) __half Xs[128 * G2_ROWS];   // 16 KB
    __shared__ __align__(16) float  Ws[128 * NC];        // 20 KB

    int tid  = threadIdx.x;
    int row0 = blockIdx.x * G2_ROWS;

    for (int i = tid; i < 128 * NC / 4; i += 320)
        ((float4*)Ws)[i] = ((const float4*)W2)[i];

    for (int i = tid; i < G2_ROWS * 16; i += 320) {
        int m  = i / 16;
        int k8 = (i % 16) * 8;
        uint4 v = make_uint4(0u, 0u, 0u, 0u);
        if (row0 + m < M)
            v = ((const uint4*)(g_hd + (size_t)(row0 + m) * 128))[i % 16];
        __half* hp = (__half*)&v;
#pragma unroll
        for (int j = 0; j < 8; j++) Xs[(k8 + j) * G2_ROWS + m] = hp[j];
    }
    __syncthreads();

    int w    = tid >> 5;
    int lane = tid & 31;
    int c0   = w * 4;

    uint64_t a00 = pack2(0.f, 0.f), a01 = a00;
    uint64_t a10 = a00, a11 = a00;

#pragma unroll 4
    for (int k = 0; k < 128; k++) {
        __half2 xv = *(__half2*)&Xs[k * G2_ROWS + 2 * lane];
        float2  xf = __half22float2(xv);
        float4  wv = *(const float4*)&Ws[k * NC + c0];
        uint64_t w01 = pack2(wv.x, wv.y);
        uint64_t w23 = pack2(wv.z, wv.w);
        uint64_t x0  = pack2(xf.x, xf.x);
        uint64_t x1  = pack2(xf.y, xf.y);
        fma2(a00, x0, w01); fma2(a01, x0, w23);
        fma2(a10, x1, w01); fma2(a11, x1, w23);
    }

    int m0 = row0 + 2 * lane;
    if (m0 < M) {
        float2 p0 = unpack2(a00), p1 = unpack2(a01);
        __half2 h0 = __float22half2_rn(p0);
        __half2 h1 = __float22half2_rn(p1);
        uint2 pkt; pkt.x = *(uint32_t*)&h0; pkt.y = *(uint32_t*)&h1;
        *(uint2*)(g_t2 + (size_t)m0 * NC + c0) = pkt;
    }
    if (m0 + 1 < M) {
        float2 p0 = unpack2(a10), p1 = unpack2(a11);
        __half2 h0 = __float22half2_rn(p0);
        __half2 h1 = __float22half2_rn(p1);
        uint2 pkt; pkt.x = *(uint32_t*)&h0; pkt.y = *(uint32_t*)&h1;
        *(uint2*)(g_t2 + (size_t)(m0 + 1) * NC + c0) = pkt;
    }
}

// ---------------- agg2: out = A_norm @ t2 + b2  (t2 fp16, out fp32) ------
__global__ void k_agg2(const float* __restrict__ b2,
                       float* __restrict__ out,
                       int N) {
    int warp = threadIdx.x >> 5;
    int lane = threadIdx.x & 31;
    int n = blockIdx.x * (blockDim.x >> 5) + warp;
    if (n >= N) return;

    bool active = lane < 20;
    float di = g_dinv[n];
    float wself = di * di;

    float2 a = make_float2(0.f, 0.f);
    if (active) {
        __half2 v = ((const __half2*)(g_t2 + (size_t)n * NC))[lane];
        float2 f = __half22float2(v);
        a.x = f.x * wself;
        a.y = f.y * wself;
    }

    int e  = g_rowptr[n];
    int e1 = g_rowptr[n + 1];

    for (; e + 8 <= e1; e += 8) {
        int     si[8];
        float   wi[8];
        __half2 vi[8];
#pragma unroll
        for (int u = 0; u < 8; u++) si[u] = g_csr_src[e + u];
#pragma unroll
        for (int u = 0; u < 8; u++) wi[u] = g_dinv[si[u]] * di;
#pragma unroll
        for (int u = 0; u < 8; u++)
            vi[u] = active
                  ? ((const __half2*)(g_t2 + (size_t)si[u] * NC))[lane]
                  : __half2();
#pragma unroll
        for (int u = 0; u < 8; u++) {
            float2 f = __half22float2(vi[u]);
            a.x = fmaf(f.x, wi[u], a.x);
            a.y = fmaf(f.y, wi[u], a.y);
        }
    }
    for (; e < e1; e++) {
        int s   = g_csr_src[e];
        float w = g_dinv[s] * di;
        if (active) {
            __half2 v = ((const __half2*)(g_t2 + (size_t)s * NC))[lane];
            float2 f = __half22float2(v);
            a.x = fmaf(f.x, w, a.x);
            a.y = fmaf(f.y, w, a.y);
        }
    }

    if (active) {
        float2 bv = ((const float2*)b2)[lane];
        float2 o = make_float2(a.x + bv.x, a.y + bv.y);
        *(float2*)(out + (size_t)n * NC + 2 * lane) = o;
    }
}

// ---------------- launch ----------------
// k_gemm1 placed 4th: that's the launch slot ncu's -s 5 -c 1 captures,
// giving visibility into the new tensor-core GEMM next round.
extern "C" void kernel_launch(void* const* d_in, const int* in_sizes, int n_in,
                              void* d_out, int out_size) {
    const float* x  = (const float*)d_in[0];
    const int*   ei = (const int*)d_in[1];
    const float* W1 = (const float*)d_in[2];
    const float* b1 = (const float*)d_in[3];
    const float* W2 = (const float*)d_in[4];
    const float* b2 = (const float*)d_in[5];
    float* out = (float*)d_out;

    const int N = N_NODES;
    const int E = N_EDGES;
    const int nb = (N + 1023) / 1024;

    k_zero  <<<(N + 255) / 256, 256>>>(N);
    k_count <<<(E + 255) / 256, 256>>>(ei, E);
    k_scan1 <<<nb, 1024>>>(N);
    k_gemm1 <<<(N + 127) / 128, 256>>>(x, W1, N);   // independent of CSR
    k_scan2 <<<1, 128>>>(nb, N);
    k_scan3 <<<nb, 1024>>>(N);
    k_fill  <<<(E + 255) / 256, 256>>>(ei, E);
    k_agg1  <<<(N + 7) / 8, 256>>>(b1, N);
    k_gemm2 <<<(N + G2_ROWS - 1) / G2_ROWS, 320>>>(W2, N);
    k_agg2  <<<(N + 7) / 8, 256>>>(b2, out, N);
}

// round 9
// speedup vs baseline: 1.9037x; 1.0382x over previous
#include <cuda_runtime.h>
#include <cuda_fp16.h>
#include <stdint.h>

#define N_NODES 100000
#define N_EDGES 1600000
#define NF      128
#define NC      40

// ---------------- static scratch (no allocations allowed) ----------------
static __device__ __half g_h [(size_t)N_NODES * NF];        // 25.6 MB
static __device__ __half g_hd[(size_t)N_NODES * NF];        // 25.6 MB
static __device__ __half g_t2[(size_t)N_NODES * NC + 64];   // 8 MB (+pad)
static __device__ float  g_dinv[N_NODES];
static __device__ int    g_cnt[N_NODES];
static __device__ int    g_rowptr[N_NODES + 1];
static __device__ int    g_cursor[N_NODES];
static __device__ int    g_csr_src[N_EDGES];                // 6.4 MB
static __device__ int    g_blocksum[128];

// ---------------- packed f32x2 helpers (Blackwell dual-rate fp32) --------
__device__ __forceinline__ uint64_t pack2(float lo, float hi) {
    uint64_t r;
    asm("mov.b64 %0, {%1, %2};" : "=l"(r) : "f"(lo), "f"(hi));
    return r;
}
__device__ __forceinline__ void fma2(uint64_t& d, uint64_t a, uint64_t b) {
    asm("fma.rn.f32x2 %0, %1, %2, %0;" : "+l"(d) : "l"(a), "l"(b));
}
__device__ __forceinline__ float2 unpack2(uint64_t v) {
    float2 f;
    asm("mov.b64 {%0, %1}, %2;" : "=f"(f.x), "=f"(f.y) : "l"(v));
    return f;
}

// ---------------- threefry2x32, key = (0, 42) ----------------
__device__ __forceinline__ uint32_t rotl32(uint32_t x, int r) {
    return (x << r) | (x >> (32 - r));
}

__device__ __forceinline__ void threefry_0_42(uint32_t& x0, uint32_t& x1) {
    const uint32_t K1 = 0u;
    const uint32_t K2 = 42u;
    const uint32_t KC = 0x1BD11BDAu ^ K1 ^ K2;
#define TF_ROUND(r) { x0 += x1; x1 = rotl32(x1, r); x1 ^= x0; }
    x0 += K1; x1 += K2;
    TF_ROUND(13) TF_ROUND(15) TF_ROUND(26) TF_ROUND(6)
    x0 += K2; x1 += KC + 1u;
    TF_ROUND(17) TF_ROUND(29) TF_ROUND(16) TF_ROUND(24)
    x0 += KC; x1 += K1 + 2u;
    TF_ROUND(13) TF_ROUND(15) TF_ROUND(26) TF_ROUND(6)
    x0 += K1; x1 += K2 + 3u;
    TF_ROUND(17) TF_ROUND(29) TF_ROUND(16) TF_ROUND(24)
    x0 += K2; x1 += KC + 4u;
    TF_ROUND(13) TF_ROUND(15) TF_ROUND(26) TF_ROUND(6)
    x0 += KC; x1 += K1 + 5u;
#undef TF_ROUND
}

__device__ __forceinline__ float drop_scale(uint32_t i) {
    uint32_t a = 0u, b = i;
    threefry_0_42(a, b);
    return ((a ^ b) >> 31) ? 2.0f : 0.0f;
}

// ---------------- small kernels: degree / CSR build ----------------
__global__ void k_zero(int N) {
    int i = blockIdx.x * blockDim.x + threadIdx.x;
    if (i < N) g_cnt[i] = 0;
}

__global__ void k_count(const int* __restrict__ ei, int E) {
    int e = blockIdx.x * blockDim.x + threadIdx.x;
    if (e < E) atomicAdd(&g_cnt[ei[E + e]], 1);
}

__global__ void k_scan1(int N) {
    __shared__ int s[1024];
    int t = threadIdx.x;
    int i = blockIdx.x * 1024 + t;
    s[t] = (i < N) ? g_cnt[i] : 0;
    __syncthreads();
    for (int off = 512; off > 0; off >>= 1) {
        if (t < off) s[t] += s[t + off];
        __syncthreads();
    }
    if (t == 0) g_blocksum[blockIdx.x] = s[0];
}

__global__ void k_scan2(int nb, int N) {
    __shared__ int s[128];
    int t = threadIdx.x;
    int v = (t < nb) ? g_blocksum[t] : 0;
    s[t] = v;
    __syncthreads();
    for (int off = 1; off < 128; off <<= 1) {
        int x = (t >= off) ? s[t - off] : 0;
        __syncthreads();
        s[t] += x;
        __syncthreads();
    }
    if (t < nb) g_blocksum[t] = s[t] - v;
    if (t == 127) g_rowptr[N] = s[127];
}

__global__ void k_scan3(int N) {
    __shared__ int s[1024];
    int t = threadIdx.x;
    int i = blockIdx.x * 1024 + t;
    int v = (i < N) ? g_cnt[i] : 0;
    s[t] = v;
    __syncthreads();
    for (int off = 1; off < 1024; off <<= 1) {
        int x = (t >= off) ? s[t - off] : 0;
        __syncthreads();
        s[t] += x;
        __syncthreads();
    }
    if (i < N) {
        int excl = s[t] - v + g_blocksum[blockIdx.x];
        g_rowptr[i] = excl;
        g_cursor[i] = excl;
        g_dinv[i]   = rsqrtf((float)(v + 1));
    }
}

__global__ void k_fill(const int* __restrict__ ei, int E) {
    int e = blockIdx.x * blockDim.x + threadIdx.x;
    if (e < E) {
        int d   = ei[E + e];
        int pos = atomicAdd(&g_cursor[d], 1);
        g_csr_src[pos] = ei[e];
    }
}

// ---------------- GEMM1: h = x @ W1, fp16 tensor cores (mma.sync) --------
// Block = 512 threads (16 warps), tile 128 rows x 128 cols, K=128.
// W1 transposed+converted once to smem; A-fragments loaded directly from x
// as float2 and converted in registers (no As tile, no k-loop syncs).
// Warp w: rows (w>>1)*16, cols (w&1)*64 (8 n-tiles, 32 acc regs).
#define WT_PAD 136   // halves per Wt row (conflict-spread B-frag reads)

__device__ __forceinline__ void mma16816(float c[4],
                                         uint32_t a0, uint32_t a1,
                                         uint32_t a2, uint32_t a3,
                                         uint32_t b0, uint32_t b1) {
    asm volatile(
        "mma.sync.aligned.m16n8k16.row.col.f32.f16.f16.f32 "
        "{%0,%1,%2,%3}, {%4,%5,%6,%7}, {%8,%9}, {%0,%1,%2,%3};"
        : "+f"(c[0]), "+f"(c[1]), "+f"(c[2]), "+f"(c[3])
        : "r"(a0), "r"(a1), "r"(a2), "r"(a3), "r"(b0), "r"(b1));
}

__device__ __forceinline__ uint32_t f2h2(float2 v) {
    __half2 h = __floats2half2_rn(v.x, v.y);
    return *(uint32_t*)&h;
}

__global__ __launch_bounds__(512) void k_gemm1(const float* __restrict__ x,
                                               const float* __restrict__ W,
                                               int M) {
    __shared__ __align__(16) __half Wt[128 * WT_PAD];  // ~34 KB

    int tid  = threadIdx.x;
    int row0 = blockIdx.x * 128;

    // stage Wt[n][k] = (half)W[k][n]
    for (int i = tid; i < 128 * 32; i += 512) {
        int n  = i & 127;
        int kg = i >> 7;
#pragma unroll
        for (int j = 0; j < 4; j++) {
            int k = 4 * kg + j;
            Wt[n * WT_PAD + k] = __float2half(W[(size_t)k * 128 + n]);
        }
    }
    __syncthreads();

    int warp = tid >> 5;
    int lane = tid & 31;
    int g = lane >> 2;       // 0..7
    int t = lane & 3;        // 0..3
    int rg = warp >> 1;      // 0..7 row group
    int ch = warp & 1;       // 0..1 col half

    int r_lo = row0 + rg * 16 + g;
    int r_hi = r_lo + 8;
    bool lo_ok = r_lo < M;
    bool hi_ok = r_hi < M;
    const float* xlo = x + (size_t)r_lo * 128 + 2 * t;
    const float* xhi = x + (size_t)r_hi * 128 + 2 * t;

    float acc[8][4];
#pragma unroll
    for (int nt = 0; nt < 8; nt++)
#pragma unroll
        for (int j = 0; j < 4; j++) acc[nt][j] = 0.f;

#pragma unroll
    for (int k0 = 0; k0 < 128; k0 += 16) {
        uint32_t a0 = 0u, a1 = 0u, a2 = 0u, a3 = 0u;
        if (lo_ok) {
            a0 = f2h2(*(const float2*)(xlo + k0));
            a2 = f2h2(*(const float2*)(xlo + k0 + 8));
        }
        if (hi_ok) {
            a1 = f2h2(*(const float2*)(xhi + k0));
            a3 = f2h2(*(const float2*)(xhi + k0 + 8));
        }
#pragma unroll
        for (int nt = 0; nt < 8; nt++) {
            const __half* wp = &Wt[(ch * 64 + nt * 8 + g) * WT_PAD + k0 + 2 * t];
            uint32_t b0 = *(uint32_t*)(wp);
            uint32_t b1 = *(uint32_t*)(wp + 8);
            mma16816(acc[nt], a0, a1, a2, a3, b0, b1);
        }
    }

    // epilogue: store fp16 h
#pragma unroll
    for (int nt = 0; nt < 8; nt++) {
        int col = ch * 64 + nt * 8 + 2 * t;
        if (lo_ok) {
            __half2 hv = __floats2half2_rn(acc[nt][0], acc[nt][1]);
            *(uint32_t*)(g_h + (size_t)r_lo * 128 + col) = *(uint32_t*)&hv;
        }
        if (hi_ok) {
            __half2 hv = __floats2half2_rn(acc[nt][2], acc[nt][3]);
            *(uint32_t*)(g_h + (size_t)r_hi * 128 + col) = *(uint32_t*)&hv;
        }
    }
}

// ---- agg1: hd = dropout(relu(A_norm @ h + b1)), stored fp16 ----
__device__ __forceinline__ void acc_half4(float4& acc, uint2 raw, float w) {
    __half2 lo = *(__half2*)&raw.x;
    __half2 hi = *(__half2*)&raw.y;
    float2 f0 = __half22float2(lo);
    float2 f1 = __half22float2(hi);
    acc.x = fmaf(f0.x, w, acc.x);
    acc.y = fmaf(f0.y, w, acc.y);
    acc.z = fmaf(f1.x, w, acc.z);
    acc.w = fmaf(f1.y, w, acc.w);
}

__global__ void k_agg1(const float* __restrict__ b1, int N) {
    int warp = threadIdx.x >> 5;
    int lane = threadIdx.x & 31;
    int n = blockIdx.x * (blockDim.x >> 5) + warp;
    if (n >= N) return;

    float di = g_dinv[n];
    float wself = di * di;

    float4 acc = make_float4(0.f, 0.f, 0.f, 0.f);
    {
        uint2 raw = ((const uint2*)(g_h + (size_t)n * 128))[lane];
        acc_half4(acc, raw, wself);
    }

    int e  = g_rowptr[n];
    int e1 = g_rowptr[n + 1];

    for (; e + 8 <= e1; e += 8) {
        int   si[8];
        float wi[8];
        uint2 vi[8];
#pragma unroll
        for (int u = 0; u < 8; u++) si[u] = g_csr_src[e + u];
#pragma unroll
        for (int u = 0; u < 8; u++) wi[u] = g_dinv[si[u]] * di;
#pragma unroll
        for (int u = 0; u < 8; u++)
            vi[u] = ((const uint2*)(g_h + (size_t)si[u] * 128))[lane];
#pragma unroll
        for (int u = 0; u < 8; u++) acc_half4(acc, vi[u], wi[u]);
    }
    for (; e < e1; e++) {
        int s   = g_csr_src[e];
        float w = g_dinv[s] * di;
        uint2 raw = ((const uint2*)(g_h + (size_t)s * 128))[lane];
        acc_half4(acc, raw, w);
    }

    uint32_t mi = (uint32_t)n * 128u + (uint32_t)lane * 4u;
    float4 bb = ((const float4*)b1)[lane];
    float f0 = fmaxf(acc.x + bb.x, 0.f) * drop_scale(mi + 0u);
    float f1 = fmaxf(acc.y + bb.y, 0.f) * drop_scale(mi + 1u);
    float f2 = fmaxf(acc.z + bb.z, 0.f) * drop_scale(mi + 2u);
    float f3 = fmaxf(acc.w + bb.w, 0.f) * drop_scale(mi + 3u);

    __half2 h0 = __floats2half2_rn(f0, f1);
    __half2 h1 = __floats2half2_rn(f2, f3);
    uint2 pkt;
    pkt.x = *(uint32_t*)&h0;
    pkt.y = *(uint32_t*)&h1;
    ((uint2*)(g_hd + (size_t)n * 128))[lane] = pkt;
}

// ---------------- GEMM2: t2 = hd @ W2  (fp16 in, fp32 acc, fp16 out) -----
#define G2_ROWS 64
__global__ __launch_bounds__(320) void k_gemm2(const float* __restrict__ W2,
                                               int M) {
    __shared__ __align__(16) __half Xs[128 * G2_ROWS];   // 16 KB
    __shared__ __align__(16) float  Ws[128 * NC];        // 20 KB

    int tid  = threadIdx.x;
    int row0 = blockIdx.x * G2_ROWS;

    for (int i = tid; i < 128 * NC / 4; i += 320)
        ((float4*)Ws)[i] = ((const float4*)W2)[i];

    for (int i = tid; i < G2_ROWS * 16; i += 320) {
        int m  = i / 16;
        int k8 = (i % 16) * 8;
        uint4 v = make_uint4(0u, 0u, 0u, 0u);
        if (row0 + m < M)
            v = ((const uint4*)(g_hd + (size_t)(row0 + m) * 128))[i % 16];
        __half* hp = (__half*)&v;
#pragma unroll
        for (int j = 0; j < 8; j++) Xs[(k8 + j) * G2_ROWS + m] = hp[j];
    }
    __syncthreads();

    int w    = tid >> 5;
    int lane = tid & 31;
    int c0   = w * 4;

    uint64_t a00 = pack2(0.f, 0.f), a01 = a00;
    uint64_t a10 = a00, a11 = a00;

#pragma unroll 4
    for (int k = 0; k < 128; k++) {
        __half2 xv = *(__half2*)&Xs[k * G2_ROWS + 2 * lane];
        float2  xf = __half22float2(xv);
        float4  wv = *(const float4*)&Ws[k * NC + c0];
        uint64_t w01 = pack2(wv.x, wv.y);
        uint64_t w23 = pack2(wv.z, wv.w);
        uint64_t x0  = pack2(xf.x, xf.x);
        uint64_t x1  = pack2(xf.y, xf.y);
        fma2(a00, x0, w01); fma2(a01, x0, w23);
        fma2(a10, x1, w01); fma2(a11, x1, w23);
    }

    int m0 = row0 + 2 * lane;
    if (m0 < M) {
        float2 p0 = unpack2(a00), p1 = unpack2(a01);
        __half2 h0 = __float22half2_rn(p0);
        __half2 h1 = __float22half2_rn(p1);
        uint2 pkt; pkt.x = *(uint32_t*)&h0; pkt.y = *(uint32_t*)&h1;
        *(uint2*)(g_t2 + (size_t)m0 * NC + c0) = pkt;
    }
    if (m0 + 1 < M) {
        float2 p0 = unpack2(a10), p1 = unpack2(a11);
        __half2 h0 = __float22half2_rn(p0);
        __half2 h1 = __float22half2_rn(p1);
        uint2 pkt; pkt.x = *(uint32_t*)&h0; pkt.y = *(uint32_t*)&h1;
        *(uint2*)(g_t2 + (size_t)(m0 + 1) * NC + c0) = pkt;
    }
}

// ---------------- agg2: out = A_norm @ t2 + b2  (t2 fp16, out fp32) ------
__global__ void k_agg2(const float* __restrict__ b2,
                       float* __restrict__ out,
                       int N) {
    int warp = threadIdx.x >> 5;
    int lane = threadIdx.x & 31;
    int n = blockIdx.x * (blockDim.x >> 5) + warp;
    if (n >= N) return;

    bool active = lane < 20;
    float di = g_dinv[n];
    float wself = di * di;

    float2 a = make_float2(0.f, 0.f);
    if (active) {
        __half2 v = ((const __half2*)(g_t2 + (size_t)n * NC))[lane];
        float2 f = __half22float2(v);
        a.x = f.x * wself;
        a.y = f.y * wself;
    }

    int e  = g_rowptr[n];
    int e1 = g_rowptr[n + 1];

    for (; e + 8 <= e1; e += 8) {
        int     si[8];
        float   wi[8];
        __half2 vi[8];
#pragma unroll
        for (int u = 0; u < 8; u++) si[u] = g_csr_src[e + u];
#pragma unroll
        for (int u = 0; u < 8; u++) wi[u] = g_dinv[si[u]] * di;
#pragma unroll
        for (int u = 0; u < 8; u++)
            vi[u] = active
                  ? ((const __half2*)(g_t2 + (size_t)si[u] * NC))[lane]
                  : __half2();
#pragma unroll
        for (int u = 0; u < 8; u++) {
            float2 f = __half22float2(vi[u]);
            a.x = fmaf(f.x, wi[u], a.x);
            a.y = fmaf(f.y, wi[u], a.y);
        }
    }
    for (; e < e1; e++) {
        int s   = g_csr_src[e];
        float w = g_dinv[s] * di;
        if (active) {
            __half2 v = ((const __half2*)(g_t2 + (size_t)s * NC))[lane];
            float2 f = __half22float2(v);
            a.x = fmaf(f.x, w, a.x);
            a.y = fmaf(f.y, w, a.y);
        }
    }

    if (active) {
        float2 bv = ((const float2*)b2)[lane];
        float2 o = make_float2(a.x + bv.x, a.y + bv.y);
        *(float2*)(out + (size_t)n * NC + 2 * lane) = o;
    }
}

// ---------------- launch ----------------
// k_gemm1 stays 4th: ncu's -s 5 -c 1 captures that slot.
extern "C" void kernel_launch(void* const* d_in, const int* in_sizes, int n_in,
                              void* d_out, int out_size) {
    const float* x  = (const float*)d_in[0];
    const int*   ei = (const int*)d_in[1];
    const float* W1 = (const float*)d_in[2];
    const float* b1 = (const float*)d_in[3];
    const float* W2 = (const float*)d_in[4];
    const float* b2 = (const float*)d_in[5];
    float* out = (float*)d_out;

    const int N = N_NODES;
    const int E = N_EDGES;
    const int nb = (N + 1023) / 1024;

    k_zero  <<<(N + 255) / 256, 256>>>(N);
    k_count <<<(E + 255) / 256, 256>>>(ei, E);
    k_scan1 <<<nb, 1024>>>(N);
    k_gemm1 <<<(N + 127) / 128, 512>>>(x, W1, N);   // independent of CSR
    k_scan2 <<<1, 128>>>(nb, N);
    k_scan3 <<<nb, 1024>>>(N);
    k_fill  <<<(E + 255) / 256, 256>>>(ei, E);
    k_agg1  <<<(N + 7) / 8, 256>>>(b1, N);
    k_gemm2 <<<(N + G2_ROWS - 1) / G2_ROWS, 320>>>(W2, N);
    k_agg2  <<<(N + 7) / 8, 256>>>(b2, out, N);
}